// round 2
// baseline (speedup 1.0000x reference)
#include <cuda_runtime.h>

#define BB 2
#define SS 2048
#define EE 1024
#define HH 16
#define DD 64
#define MTOT (BB*SS)    // 4096
#define HD (HH*DD)      // 1024

// Scratch (device globals: allocation-free per harness rules)
__device__ float g_Q[(size_t)MTOT * HD];
__device__ float g_K[(size_t)MTOT * HD];
__device__ float g_V[(size_t)MTOT * HD];
__device__ float g_O[(size_t)MTOT * HD];

// ---------------------------------------------------------------------------
// GEMM: C[m,n] = sum_k A[m,k] * W[n,k]   (TN, both K-major row-major)
// 128x128 tile, BK=32, 256 threads, 8x8 micro-tile with strided ownership:
//   thread(ty,tx) owns rows {ty+16i} and cols {tx+16j}.
// smem stride 33 (== 1 mod 32) -> conflict-free scalar LDS.
// ---------------------------------------------------------------------------
__global__ __launch_bounds__(256) void qkv_gemm_kernel(
    const float* __restrict__ A,
    const float* __restrict__ Wq,
    const float* __restrict__ Wk,
    const float* __restrict__ Wv)
{
    __shared__ float As[128 * 33];
    __shared__ float Bs[128 * 33];

    const float* W = (blockIdx.z == 0) ? Wq : (blockIdx.z == 1 ? Wk : Wv);
    float* Cg      = (blockIdx.z == 0) ? g_Q : (blockIdx.z == 1 ? g_K : g_V);

    const int tid = threadIdx.x;
    const int tx = tid & 15, ty = tid >> 4;
    const int bn = blockIdx.x * 128;
    const int bm = blockIdx.y * 128;

    float acc[8][8];
#pragma unroll
    for (int i = 0; i < 8; i++)
#pragma unroll
        for (int j = 0; j < 8; j++) acc[i][j] = 0.0f;

    for (int kt = 0; kt < EE; kt += 32) {
        __syncthreads();
#pragma unroll
        for (int p = 0; p < 4; p++) {
            int v = tid + p * 256;
            int r = v >> 3;
            int kv = (v & 7) * 4;
            float4 a = *(const float4*)(A + (size_t)(bm + r) * EE + kt + kv);
            As[r * 33 + kv + 0] = a.x;
            As[r * 33 + kv + 1] = a.y;
            As[r * 33 + kv + 2] = a.z;
            As[r * 33 + kv + 3] = a.w;
            float4 w = *(const float4*)(W + (size_t)(bn + r) * EE + kt + kv);
            Bs[r * 33 + kv + 0] = w.x;
            Bs[r * 33 + kv + 1] = w.y;
            Bs[r * 33 + kv + 2] = w.z;
            Bs[r * 33 + kv + 3] = w.w;
        }
        __syncthreads();
#pragma unroll
        for (int k = 0; k < 32; k++) {
            float a_[8], b_[8];
#pragma unroll
            for (int i = 0; i < 8; i++) a_[i] = As[(ty + 16 * i) * 33 + k];
#pragma unroll
            for (int j = 0; j < 8; j++) b_[j] = Bs[(tx + 16 * j) * 33 + k];
#pragma unroll
            for (int i = 0; i < 8; i++)
#pragma unroll
                for (int j = 0; j < 8; j++) acc[i][j] += a_[i] * b_[j];
        }
    }

#pragma unroll
    for (int i = 0; i < 8; i++)
#pragma unroll
        for (int j = 0; j < 8; j++)
            Cg[(size_t)(bm + ty + 16 * i) * HD + bn + tx + 16 * j] = acc[i][j];
}

// Out projection: C = g_O @ Wu^T + bu[n] + emb[m,n]  -> d_out
__global__ __launch_bounds__(256) void out_gemm_kernel(
    const float* __restrict__ Wu,
    const float* __restrict__ bu,
    const float* __restrict__ emb,
    float* __restrict__ out)
{
    __shared__ float As[128 * 33];
    __shared__ float Bs[128 * 33];

    const int tid = threadIdx.x;
    const int tx = tid & 15, ty = tid >> 4;
    const int bn = blockIdx.x * 128;
    const int bm = blockIdx.y * 128;

    float acc[8][8];
#pragma unroll
    for (int i = 0; i < 8; i++)
#pragma unroll
        for (int j = 0; j < 8; j++) acc[i][j] = 0.0f;

    for (int kt = 0; kt < HD; kt += 32) {
        __syncthreads();
#pragma unroll
        for (int p = 0; p < 4; p++) {
            int v = tid + p * 256;
            int r = v >> 3;
            int kv = (v & 7) * 4;
            float4 a = *(const float4*)(g_O + (size_t)(bm + r) * HD + kt + kv);
            As[r * 33 + kv + 0] = a.x;
            As[r * 33 + kv + 1] = a.y;
            As[r * 33 + kv + 2] = a.z;
            As[r * 33 + kv + 3] = a.w;
            float4 w = *(const float4*)(Wu + (size_t)(bn + r) * HD + kt + kv);
            Bs[r * 33 + kv + 0] = w.x;
            Bs[r * 33 + kv + 1] = w.y;
            Bs[r * 33 + kv + 2] = w.z;
            Bs[r * 33 + kv + 3] = w.w;
        }
        __syncthreads();
#pragma unroll
        for (int k = 0; k < 32; k++) {
            float a_[8], b_[8];
#pragma unroll
            for (int i = 0; i < 8; i++) a_[i] = As[(ty + 16 * i) * 33 + k];
#pragma unroll
            for (int j = 0; j < 8; j++) b_[j] = Bs[(tx + 16 * j) * 33 + k];
#pragma unroll
            for (int i = 0; i < 8; i++)
#pragma unroll
                for (int j = 0; j < 8; j++) acc[i][j] += a_[i] * b_[j];
        }
    }

#pragma unroll
    for (int i = 0; i < 8; i++) {
        int m = bm + ty + 16 * i;
#pragma unroll
        for (int j = 0; j < 8; j++) {
            int n = bn + tx + 16 * j;
            out[(size_t)m * EE + n] = acc[i][j] + bu[n] + emb[(size_t)m * EE + n];
        }
    }
}

// ---------------------------------------------------------------------------
// LayerNorm over D=64 per (tensor, row, head). One warp per task.
// Folds the attention 1/sqrt(D)=0.125 scale into Q.
// ---------------------------------------------------------------------------
__global__ __launch_bounds__(256) void ln_kernel(
    const float* __restrict__ qw, const float* __restrict__ qb,
    const float* __restrict__ kw, const float* __restrict__ kb)
{
    int warp = (blockIdx.x * blockDim.x + threadIdx.x) >> 5;
    int lane = threadIdx.x & 31;
    int tensor = warp >> 16;        // 65536 warps per tensor
    int rem = warp & 65535;
    int row = rem >> 4;
    int head = rem & 15;

    float* p = (tensor ? g_K : g_Q) + (size_t)row * HD + head * DD;
    const float* w = tensor ? kw : qw;
    const float* bb = tensor ? kb : qb;
    const float scale = tensor ? 1.0f : 0.125f;

    float x0 = p[lane];
    float x1 = p[lane + 32];
    float s = x0 + x1;
    float sq = x0 * x0 + x1 * x1;
#pragma unroll
    for (int o = 16; o > 0; o >>= 1) {
        s  += __shfl_xor_sync(0xffffffffu, s, o);
        sq += __shfl_xor_sync(0xffffffffu, sq, o);
    }
    float mean = s * (1.0f / 64.0f);
    float var = sq * (1.0f / 64.0f) - mean * mean;
    float inv = rsqrtf(var + 1e-5f);
    p[lane]      = ((x0 - mean) * inv * w[lane]      + bb[lane])      * scale;
    p[lane + 32] = ((x1 - mean) * inv * w[lane + 32] + bb[lane + 32]) * scale;
}

// ---------------------------------------------------------------------------
// Flash-style attention. grid (S/128, B*H). 256 threads.
// Q tile 128x64, KV tile 128. S/P 128x128 (8x8 per thread), O 128x64 (8x4).
// Q/K/V smem stride 65 (64-wide tiles); P smem stride 129 (128-wide tile).
// Both strides ==1 mod 32 -> conflict-free scalar LDS.
// ---------------------------------------------------------------------------
#define PSTR 129
__global__ __launch_bounds__(256, 1) void attn_kernel()
{
    extern __shared__ float sm[];
    float* Qs = sm;                    // 128*65
    float* Ks = sm + 128 * 65;         // 128*65
    float* Vs = sm + 2 * 128 * 65;     // 128*65 (64 cols used)
    float* Ps = sm + 3 * 128 * 65;     // 128*PSTR (128 cols used)

    const int tid = threadIdx.x;
    const int tx = tid & 15, ty = tid >> 4;
    const int q0 = blockIdx.x * 128;
    const int bh = blockIdx.y;
    const int b = bh >> 4, h = bh & 15;

    const float* Qg = g_Q + (size_t)(b * SS + q0) * HD + h * DD;

    // load Q tile (128 rows x 64 d)
#pragma unroll
    for (int p = 0; p < 8; p++) {
        int v = tid + p * 256;
        int r = v >> 4;
        int dv = (v & 15) * 4;
        float4 t = *(const float4*)(Qg + (size_t)r * HD + dv);
        float* dst = Qs + r * 65 + dv;
        dst[0] = t.x; dst[1] = t.y; dst[2] = t.z; dst[3] = t.w;
    }

    float o[8][4];
    float m_i[8], l_i[8];
#pragma unroll
    for (int i = 0; i < 8; i++) {
        m_i[i] = -1e30f;
        l_i[i] = 0.0f;
#pragma unroll
        for (int j = 0; j < 4; j++) o[i][j] = 0.0f;
    }

    for (int kv0 = 0; kv0 < SS; kv0 += 128) {
        __syncthreads();  // protect Ks/Vs/Ps from previous iteration readers

        const float* Kg = g_K + (size_t)(b * SS + kv0) * HD + h * DD;
        const float* Vg = g_V + (size_t)(b * SS + kv0) * HD + h * DD;
#pragma unroll
        for (int p = 0; p < 8; p++) {
            int v = tid + p * 256;
            int r = v >> 4;
            int dv = (v & 15) * 4;
            float4 tk = *(const float4*)(Kg + (size_t)r * HD + dv);
            float* dk = Ks + r * 65 + dv;
            dk[0] = tk.x; dk[1] = tk.y; dk[2] = tk.z; dk[3] = tk.w;
            float4 tv = *(const float4*)(Vg + (size_t)r * HD + dv);
            float* dv_ = Vs + r * 65 + dv;
            dv_[0] = tv.x; dv_[1] = tv.y; dv_[2] = tv.z; dv_[3] = tv.w;
        }
        __syncthreads();

        // S = Q K^T  (Q already scaled by 1/8 in LN)
        float s[8][8];
#pragma unroll
        for (int i = 0; i < 8; i++)
#pragma unroll
            for (int j = 0; j < 8; j++) s[i][j] = 0.0f;

#pragma unroll 4
        for (int d = 0; d < DD; d++) {
            float a_[8], b_[8];
#pragma unroll
            for (int i = 0; i < 8; i++) a_[i] = Qs[(ty + 16 * i) * 65 + d];
#pragma unroll
            for (int j = 0; j < 8; j++) b_[j] = Ks[(tx + 16 * j) * 65 + d];
#pragma unroll
            for (int i = 0; i < 8; i++)
#pragma unroll
                for (int j = 0; j < 8; j++) s[i][j] += a_[i] * b_[j];
        }

        // online softmax per row (row r=ty+16i is shared by the 16 lanes of this ty)
#pragma unroll
        for (int i = 0; i < 8; i++) {
            float mx = s[i][0];
#pragma unroll
            for (int j = 1; j < 8; j++) mx = fmaxf(mx, s[i][j]);
#pragma unroll
            for (int off = 1; off < 16; off <<= 1)
                mx = fmaxf(mx, __shfl_xor_sync(0xffffffffu, mx, off));
            float mn = fmaxf(m_i[i], mx);
            float alpha = __expf(m_i[i] - mn);
            m_i[i] = mn;
            float rs = 0.0f;
#pragma unroll
            for (int j = 0; j < 8; j++) {
                float pv = __expf(s[i][j] - mn);
                s[i][j] = pv;
                rs += pv;
            }
#pragma unroll
            for (int off = 1; off < 16; off <<= 1)
                rs += __shfl_xor_sync(0xffffffffu, rs, off);
            l_i[i] = l_i[i] * alpha + rs;
#pragma unroll
            for (int j = 0; j < 4; j++) o[i][j] *= alpha;
#pragma unroll
            for (int j = 0; j < 8; j++)
                Ps[(ty + 16 * i) * PSTR + tx + 16 * j] = s[i][j];
        }
        __syncthreads();

        // O += P V
#pragma unroll 4
        for (int c = 0; c < 128; c++) {
            float a_[8], b_[4];
#pragma unroll
            for (int i = 0; i < 8; i++) a_[i] = Ps[(ty + 16 * i) * PSTR + c];
#pragma unroll
            for (int j = 0; j < 4; j++) b_[j] = Vs[c * 65 + tx + 16 * j];
#pragma unroll
            for (int i = 0; i < 8; i++)
#pragma unroll
                for (int j = 0; j < 4; j++) o[i][j] += a_[i] * b_[j];
        }
    }

    float* Og = g_O + (size_t)(b * SS + q0) * HD + h * DD;
#pragma unroll
    for (int i = 0; i < 8; i++) {
        float rl = 1.0f / l_i[i];
#pragma unroll
        for (int j = 0; j < 4; j++)
            Og[(size_t)(ty + 16 * i) * HD + tx + 16 * j] = o[i][j] * rl;
    }
}

// ---------------------------------------------------------------------------
extern "C" void kernel_launch(void* const* d_in, const int* in_sizes, int n_in,
                              void* d_out, int out_size)
{
    const float* emb  = (const float*)d_in[0];
    const float* Wq   = (const float*)d_in[1];
    const float* Wk   = (const float*)d_in[2];
    const float* Wv   = (const float*)d_in[3];
    const float* Wu   = (const float*)d_in[4];
    const float* bu   = (const float*)d_in[5];
    const float* qn_w = (const float*)d_in[6];
    const float* qn_b = (const float*)d_in[7];
    const float* kn_w = (const float*)d_in[8];
    const float* kn_b = (const float*)d_in[9];
    float* out = (float*)d_out;

    (void)in_sizes; (void)n_in; (void)out_size;

    const int ATTN_SMEM = (3 * 128 * 65 + 128 * PSTR) * (int)sizeof(float);  // 165888
    cudaFuncSetAttribute(attn_kernel,
                         cudaFuncAttributeMaxDynamicSharedMemorySize, ATTN_SMEM);

    // 1) QKV projections
    qkv_gemm_kernel<<<dim3(HD / 128, MTOT / 128, 3), 256>>>(emb, Wq, Wk, Wv);

    // 2) Per-head LayerNorm on Q (with 1/8 scale) and K
    ln_kernel<<<(2 * MTOT * HH) / 8, 256>>>(qn_w, qn_b, kn_w, kn_b);

    // 3) Attention
    attn_kernel<<<dim3(SS / 128, BB * HH), 256, ATTN_SMEM>>>();

    // 4) Output projection + bias + residual
    out_gemm_kernel<<<dim3(EE / 128, MTOT / 128), 256>>>(Wu, bu, emb, out);
}

// round 4
// speedup vs baseline: 1.3439x; 1.3439x over previous
#include <cuda_runtime.h>
#include <cuda_bf16.h>
#include <cstdint>

#define BB 2
#define SS 2048
#define EE 1024
#define HH 16
#define DD 64
#define MTOT (BB*SS)    // 4096
#define HD (HH*DD)      // 1024

// fp32 scratch
__device__ float g_Q[(size_t)MTOT * HD];
__device__ float g_K[(size_t)MTOT * HD];
__device__ float g_V[(size_t)MTOT * HD];
__device__ float g_O[(size_t)MTOT * HD];
// bf16 split scratch (A operand: emb first, then attention output)
__device__ __nv_bfloat16 g_Ahi[(size_t)MTOT * HD];
__device__ __nv_bfloat16 g_Alo[(size_t)MTOT * HD];
// weights hi/lo: Wq @0, Wk @1M, Wv @2M, Wu @3M
__device__ __nv_bfloat16 g_Whi[(size_t)4 * EE * HD];
__device__ __nv_bfloat16 g_Wlo[(size_t)4 * EE * HD];

// ===========================================================================
// helpers (arch-portable: cp.async + ldmatrix + mma.sync, sm_80+ PTX)
// ===========================================================================
__device__ __forceinline__ uint32_t smem_to_u32(const void* p) {
    uint32_t a;
    asm("{ .reg .u64 t; cvta.to.shared.u64 t, %1; cvt.u32.u64 %0, t; }"
        : "=r"(a) : "l"(p));
    return a;
}
__device__ __forceinline__ void cp16(uint32_t d, const void* s) {
    asm volatile("cp.async.ca.shared.global [%0], [%1], 16;" :: "r"(d), "l"(s));
}
__device__ __forceinline__ void cp_commit() {
    asm volatile("cp.async.commit_group;" ::: "memory");
}
template <int N>
__device__ __forceinline__ void cp_wait() {
    asm volatile("cp.async.wait_group %0;" :: "n"(N) : "memory");
}
__device__ __forceinline__ void ldm_x4(uint32_t* r, uint32_t addr) {
    asm volatile("ldmatrix.sync.aligned.m8n8.x4.shared.b16 {%0,%1,%2,%3}, [%4];"
        : "=r"(r[0]), "=r"(r[1]), "=r"(r[2]), "=r"(r[3]) : "r"(addr));
}
__device__ __forceinline__ void mma_bf16(float* d, const uint32_t* a, const uint32_t* b) {
    asm volatile(
        "mma.sync.aligned.m16n8k16.row.col.f32.bf16.bf16.f32 "
        "{%0,%1,%2,%3}, {%4,%5,%6,%7}, {%8,%9}, {%0,%1,%2,%3};"
        : "+f"(d[0]), "+f"(d[1]), "+f"(d[2]), "+f"(d[3])
        : "r"(a[0]), "r"(a[1]), "r"(a[2]), "r"(a[3]), "r"(b[0]), "r"(b[1]));
}

// ===========================================================================
// bf16 split conversion kernels
// ===========================================================================
__global__ __launch_bounds__(256) void split_kernel(
    const float* __restrict__ src, __nv_bfloat16* __restrict__ hi,
    __nv_bfloat16* __restrict__ lo)
{
    int i = blockIdx.x * blockDim.x + threadIdx.x;   // over n/4
    float4 v = ((const float4*)src)[i];
    __nv_bfloat16 h0 = __float2bfloat16(v.x);
    __nv_bfloat16 h1 = __float2bfloat16(v.y);
    __nv_bfloat16 h2 = __float2bfloat16(v.z);
    __nv_bfloat16 h3 = __float2bfloat16(v.w);
    __nv_bfloat16 l0 = __float2bfloat16(v.x - __bfloat162float(h0));
    __nv_bfloat16 l1 = __float2bfloat16(v.y - __bfloat162float(h1));
    __nv_bfloat16 l2 = __float2bfloat16(v.z - __bfloat162float(h2));
    __nv_bfloat16 l3 = __float2bfloat16(v.w - __bfloat162float(h3));
    ((__nv_bfloat162*)hi)[2 * i + 0] = __halves2bfloat162(h0, h1);
    ((__nv_bfloat162*)hi)[2 * i + 1] = __halves2bfloat162(h2, h3);
    ((__nv_bfloat162*)lo)[2 * i + 0] = __halves2bfloat162(l0, l1);
    ((__nv_bfloat162*)lo)[2 * i + 1] = __halves2bfloat162(l2, l3);
}

__global__ __launch_bounds__(256) void split_w_kernel(
    const float* __restrict__ Wq, const float* __restrict__ Wk,
    const float* __restrict__ Wv, const float* __restrict__ Wu)
{
    int z = blockIdx.y;
    const float* src = (z == 0) ? Wq : (z == 1) ? Wk : (z == 2) ? Wv : Wu;
    size_t base = (size_t)z * EE * HD;
    int i = blockIdx.x * blockDim.x + threadIdx.x;
    float4 v = ((const float4*)src)[i];
    __nv_bfloat16 h0 = __float2bfloat16(v.x);
    __nv_bfloat16 h1 = __float2bfloat16(v.y);
    __nv_bfloat16 h2 = __float2bfloat16(v.z);
    __nv_bfloat16 h3 = __float2bfloat16(v.w);
    __nv_bfloat16 l0 = __float2bfloat16(v.x - __bfloat162float(h0));
    __nv_bfloat16 l1 = __float2bfloat16(v.y - __bfloat162float(h1));
    __nv_bfloat16 l2 = __float2bfloat16(v.z - __bfloat162float(h2));
    __nv_bfloat16 l3 = __float2bfloat16(v.w - __bfloat162float(h3));
    ((__nv_bfloat162*)(g_Whi + base))[2 * i + 0] = __halves2bfloat162(h0, h1);
    ((__nv_bfloat162*)(g_Whi + base))[2 * i + 1] = __halves2bfloat162(h2, h3);
    ((__nv_bfloat162*)(g_Wlo + base))[2 * i + 0] = __halves2bfloat162(l0, l1);
    ((__nv_bfloat162*)(g_Wlo + base))[2 * i + 1] = __halves2bfloat162(l2, l3);
}

// ===========================================================================
// bf16x3 mma.sync GEMM: C[m,n] = sum_k A[m,k]*B[n,k]  (all leading dims 1024)
// Block 128x128, BK=32, 8 warps (warp tile 32x64), cp.async double buffer.
// 3 products: Ah*Bh + Ah*Bl + Al*Bh (Al*Bl dropped, ~1.5e-5 rel).
// If emb != nullptr: C += bu[n] + emb[m,n].
// ===========================================================================
#define ASTR 40                       // bf16 per smem row (80 B, conflict-free)
#define TILE_BYTES (128 * ASTR * 2)   // 10240
#define STAGE_BYTES (4 * TILE_BYTES)  // 40960
#define GEMM_SMEM (2 * STAGE_BYTES)   // 81920

__global__ __launch_bounds__(256, 1) void mma_gemm_kernel(
    const __nv_bfloat16* __restrict__ Ahi, const __nv_bfloat16* __restrict__ Alo,
    const __nv_bfloat16* __restrict__ Bhi_all, const __nv_bfloat16* __restrict__ Blo_all,
    float* C0, float* C1, float* C2,
    const float* __restrict__ emb, const float* __restrict__ bu)
{
    extern __shared__ char smem[];
    const uint32_t sb = smem_to_u32(smem);
    const int tid = threadIdx.x;
    const int wid = tid >> 5, lane = tid & 31;
    const int bn = blockIdx.x * 128;
    const int bm = blockIdx.y * 128;
    const int z = blockIdx.z;

    const __nv_bfloat16* Bhi = Bhi_all + (size_t)z * EE * HD;
    const __nv_bfloat16* Blo = Blo_all + (size_t)z * EE * HD;
    float* C = (z == 0) ? C0 : (z == 1) ? C1 : C2;

    const int wm = wid & 3;   // 4 warps along M
    const int wn = wid >> 2;  // 2 warps along N

    float acc[2][8][4];
#pragma unroll
    for (int mt = 0; mt < 2; mt++)
#pragma unroll
        for (int nt = 0; nt < 8; nt++)
#pragma unroll
            for (int e = 0; e < 4; e++) acc[mt][nt][e] = 0.0f;

    // precompute per-thread cp.async coords: 8 chunks of 16B
    // idx = tid + it*256; tile=idx>>9 (0:Ahi 1:Alo 2:Bhi 3:Blo); row=(idx&511)>>2; seg=idx&3
#define LOAD_STAGE(st, kt) do { \
    _Pragma("unroll") \
    for (int it = 0; it < 8; it++) { \
        int idx = tid + it * 256; \
        int tile = idx >> 9, rem = idx & 511, row = rem >> 2, seg = rem & 3; \
        const __nv_bfloat16* srcp = (tile == 0) ? Ahi : (tile == 1) ? Alo \
                                   : (tile == 2) ? Bhi : Blo; \
        int grow = ((tile < 2) ? bm : bn) + row; \
        uint32_t dst = sb + (st) * STAGE_BYTES + tile * TILE_BYTES \
                       + (uint32_t)(row * ASTR + seg * 8) * 2; \
        cp16(dst, srcp + (size_t)grow * 1024 + (kt) + seg * 8); \
    } \
    cp_commit(); \
} while (0)

    LOAD_STAGE(0, 0);

    for (int ch = 0; ch < 32; ch++) {
        if (ch < 31) { LOAD_STAGE((ch + 1) & 1, (ch + 1) * 32); cp_wait<1>(); }
        else         { cp_wait<0>(); }
        __syncthreads();

        const uint32_t base = sb + (ch & 1) * STAGE_BYTES;
        const uint32_t aAh = base;
        const uint32_t aAl = base + TILE_BYTES;
        const uint32_t aBh = base + 2 * TILE_BYTES;
        const uint32_t aBl = base + 3 * TILE_BYTES;

#pragma unroll
        for (int kk = 0; kk < 2; kk++) {
            const int k0 = kk * 16;
            uint32_t ah[2][4], al[2][4], bh[8][2], bl[8][2];
#pragma unroll
            for (int mt = 0; mt < 2; mt++) {
                int mrow = wm * 32 + mt * 16 + ((lane >> 3) & 1) * 8 + (lane & 7);
                int mcol = k0 + (lane >> 4) * 8;
                uint32_t off = (uint32_t)(mrow * ASTR + mcol) * 2;
                ldm_x4(ah[mt], aAh + off);
                ldm_x4(al[mt], aAl + off);
            }
#pragma unroll
            for (int np = 0; np < 4; np++) {
                int nrow = wn * 64 + np * 16 + (lane >> 4) * 8 + (lane & 7);
                int ncol = k0 + ((lane >> 3) & 1) * 8;
                uint32_t off = (uint32_t)(nrow * ASTR + ncol) * 2;
                uint32_t r[4];
                ldm_x4(r, aBh + off);
                bh[np * 2][0] = r[0]; bh[np * 2][1] = r[1];
                bh[np * 2 + 1][0] = r[2]; bh[np * 2 + 1][1] = r[3];
                ldm_x4(r, aBl + off);
                bl[np * 2][0] = r[0]; bl[np * 2][1] = r[1];
                bl[np * 2 + 1][0] = r[2]; bl[np * 2 + 1][1] = r[3];
            }
#pragma unroll
            for (int mt = 0; mt < 2; mt++)
#pragma unroll
                for (int nt = 0; nt < 8; nt++) mma_bf16(acc[mt][nt], ah[mt], bh[nt]);
#pragma unroll
            for (int mt = 0; mt < 2; mt++)
#pragma unroll
                for (int nt = 0; nt < 8; nt++) mma_bf16(acc[mt][nt], ah[mt], bl[nt]);
#pragma unroll
            for (int mt = 0; mt < 2; mt++)
#pragma unroll
                for (int nt = 0; nt < 8; nt++) mma_bf16(acc[mt][nt], al[mt], bh[nt]);
        }
        __syncthreads();
    }

    // epilogue
    const int tig = lane & 3, gid = lane >> 2;
#pragma unroll
    for (int mt = 0; mt < 2; mt++) {
        int r0 = bm + wm * 32 + mt * 16 + gid;
#pragma unroll
        for (int nt = 0; nt < 8; nt++) {
            int n = bn + wn * 64 + nt * 8 + tig * 2;
            float2 v0 = make_float2(acc[mt][nt][0], acc[mt][nt][1]);
            float2 v1 = make_float2(acc[mt][nt][2], acc[mt][nt][3]);
            if (emb) {
                float b0 = bu[n], b1 = bu[n + 1];
                float2 e0 = *(const float2*)(emb + (size_t)r0 * EE + n);
                float2 e1 = *(const float2*)(emb + (size_t)(r0 + 8) * EE + n);
                v0.x += b0 + e0.x; v0.y += b1 + e0.y;
                v1.x += b0 + e1.x; v1.y += b1 + e1.y;
            }
            *(float2*)(C + (size_t)r0 * 1024 + n) = v0;
            *(float2*)(C + (size_t)(r0 + 8) * 1024 + n) = v1;
        }
    }
}

// ---------------------------------------------------------------------------
// LayerNorm over D=64 per (tensor, row, head). One warp per task.
// Folds the attention 1/sqrt(D)=0.125 scale into Q.
// ---------------------------------------------------------------------------
__global__ __launch_bounds__(256) void ln_kernel(
    const float* __restrict__ qw, const float* __restrict__ qb,
    const float* __restrict__ kw, const float* __restrict__ kb)
{
    int warp = (blockIdx.x * blockDim.x + threadIdx.x) >> 5;
    int lane = threadIdx.x & 31;
    int tensor = warp >> 16;
    int rem = warp & 65535;
    int row = rem >> 4;
    int head = rem & 15;

    float* p = (tensor ? g_K : g_Q) + (size_t)row * HD + head * DD;
    const float* w = tensor ? kw : qw;
    const float* bb = tensor ? kb : qb;
    const float scale = tensor ? 1.0f : 0.125f;

    float x0 = p[lane];
    float x1 = p[lane + 32];
    float s = x0 + x1;
    float sq = x0 * x0 + x1 * x1;
#pragma unroll
    for (int o = 16; o > 0; o >>= 1) {
        s  += __shfl_xor_sync(0xffffffffu, s, o);
        sq += __shfl_xor_sync(0xffffffffu, sq, o);
    }
    float mean = s * (1.0f / 64.0f);
    float var = sq * (1.0f / 64.0f) - mean * mean;
    float inv = rsqrtf(var + 1e-5f);
    p[lane]      = ((x0 - mean) * inv * w[lane]      + bb[lane])      * scale;
    p[lane + 32] = ((x1 - mean) * inv * w[lane + 32] + bb[lane + 32]) * scale;
}

// ---------------------------------------------------------------------------
// Flash-style attention (fp32 FFMA). grid (S/128, B*H). 256 threads.
// ---------------------------------------------------------------------------
#define PSTR 129
__global__ __launch_bounds__(256, 1) void attn_kernel()
{
    extern __shared__ float sm[];
    float* Qs = sm;                    // 128*65
    float* Ks = sm + 128 * 65;
    float* Vs = sm + 2 * 128 * 65;
    float* Ps = sm + 3 * 128 * 65;     // 128*PSTR

    const int tid = threadIdx.x;
    const int tx = tid & 15, ty = tid >> 4;
    const int q0 = blockIdx.x * 128;
    const int bh = blockIdx.y;
    const int b = bh >> 4, h = bh & 15;

    const float* Qg = g_Q + (size_t)(b * SS + q0) * HD + h * DD;
#pragma unroll
    for (int p = 0; p < 8; p++) {
        int v = tid + p * 256;
        int r = v >> 4;
        int dv = (v & 15) * 4;
        float4 t = *(const float4*)(Qg + (size_t)r * HD + dv);
        float* dst = Qs + r * 65 + dv;
        dst[0] = t.x; dst[1] = t.y; dst[2] = t.z; dst[3] = t.w;
    }

    float o[8][4];
    float m_i[8], l_i[8];
#pragma unroll
    for (int i = 0; i < 8; i++) {
        m_i[i] = -1e30f;
        l_i[i] = 0.0f;
#pragma unroll
        for (int j = 0; j < 4; j++) o[i][j] = 0.0f;
    }

    for (int kv0 = 0; kv0 < SS; kv0 += 128) {
        __syncthreads();
        const float* Kg = g_K + (size_t)(b * SS + kv0) * HD + h * DD;
        const float* Vg = g_V + (size_t)(b * SS + kv0) * HD + h * DD;
#pragma unroll
        for (int p = 0; p < 8; p++) {
            int v = tid + p * 256;
            int r = v >> 4;
            int dv = (v & 15) * 4;
            float4 tk = *(const float4*)(Kg + (size_t)r * HD + dv);
            float* dk = Ks + r * 65 + dv;
            dk[0] = tk.x; dk[1] = tk.y; dk[2] = tk.z; dk[3] = tk.w;
            float4 tv = *(const float4*)(Vg + (size_t)r * HD + dv);
            float* dv_ = Vs + r * 65 + dv;
            dv_[0] = tv.x; dv_[1] = tv.y; dv_[2] = tv.z; dv_[3] = tv.w;
        }
        __syncthreads();

        float s[8][8];
#pragma unroll
        for (int i = 0; i < 8; i++)
#pragma unroll
            for (int j = 0; j < 8; j++) s[i][j] = 0.0f;

#pragma unroll 4
        for (int d = 0; d < DD; d++) {
            float a_[8], b_[8];
#pragma unroll
            for (int i = 0; i < 8; i++) a_[i] = Qs[(ty + 16 * i) * 65 + d];
#pragma unroll
            for (int j = 0; j < 8; j++) b_[j] = Ks[(tx + 16 * j) * 65 + d];
#pragma unroll
            for (int i = 0; i < 8; i++)
#pragma unroll
                for (int j = 0; j < 8; j++) s[i][j] += a_[i] * b_[j];
        }

#pragma unroll
        for (int i = 0; i < 8; i++) {
            float mx = s[i][0];
#pragma unroll
            for (int j = 1; j < 8; j++) mx = fmaxf(mx, s[i][j]);
#pragma unroll
            for (int off = 1; off < 16; off <<= 1)
                mx = fmaxf(mx, __shfl_xor_sync(0xffffffffu, mx, off));
            float mn = fmaxf(m_i[i], mx);
            float alpha = __expf(m_i[i] - mn);
            m_i[i] = mn;
            float rs = 0.0f;
#pragma unroll
            for (int j = 0; j < 8; j++) {
                float pv = __expf(s[i][j] - mn);
                s[i][j] = pv;
                rs += pv;
            }
#pragma unroll
            for (int off = 1; off < 16; off <<= 1)
                rs += __shfl_xor_sync(0xffffffffu, rs, off);
            l_i[i] = l_i[i] * alpha + rs;
#pragma unroll
            for (int j = 0; j < 4; j++) o[i][j] *= alpha;
#pragma unroll
            for (int j = 0; j < 8; j++)
                Ps[(ty + 16 * i) * PSTR + tx + 16 * j] = s[i][j];
        }
        __syncthreads();

#pragma unroll 4
        for (int c = 0; c < 128; c++) {
            float a_[8], b_[4];
#pragma unroll
            for (int i = 0; i < 8; i++) a_[i] = Ps[(ty + 16 * i) * PSTR + c];
#pragma unroll
            for (int j = 0; j < 4; j++) b_[j] = Vs[c * 65 + tx + 16 * j];
#pragma unroll
            for (int i = 0; i < 8; i++)
#pragma unroll
                for (int j = 0; j < 4; j++) o[i][j] += a_[i] * b_[j];
        }
    }

    float* Og = g_O + (size_t)(b * SS + q0) * HD + h * DD;
#pragma unroll
    for (int i = 0; i < 8; i++) {
        float rl = 1.0f / l_i[i];
#pragma unroll
        for (int j = 0; j < 4; j++)
            Og[(size_t)(ty + 16 * i) * HD + tx + 16 * j] = o[i][j] * rl;
    }
}

// ---------------------------------------------------------------------------
extern "C" void kernel_launch(void* const* d_in, const int* in_sizes, int n_in,
                              void* d_out, int out_size)
{
    const float* emb  = (const float*)d_in[0];
    const float* Wq   = (const float*)d_in[1];
    const float* Wk   = (const float*)d_in[2];
    const float* Wv   = (const float*)d_in[3];
    const float* Wu   = (const float*)d_in[4];
    const float* bu   = (const float*)d_in[5];
    const float* qn_w = (const float*)d_in[6];
    const float* qn_b = (const float*)d_in[7];
    const float* kn_w = (const float*)d_in[8];
    const float* kn_b = (const float*)d_in[9];
    float* out = (float*)d_out;

    (void)in_sizes; (void)n_in; (void)out_size;

    const int ATTN_SMEM = (3 * 128 * 65 + 128 * PSTR) * (int)sizeof(float);
    cudaFuncSetAttribute(attn_kernel,
                         cudaFuncAttributeMaxDynamicSharedMemorySize, ATTN_SMEM);
    cudaFuncSetAttribute(mma_gemm_kernel,
                         cudaFuncAttributeMaxDynamicSharedMemorySize, GEMM_SMEM);

    __nv_bfloat16 *Ahi_p, *Alo_p, *Whi_p, *Wlo_p;
    float *Q_p, *K_p, *V_p, *O_p;
    cudaGetSymbolAddress((void**)&Ahi_p, g_Ahi);
    cudaGetSymbolAddress((void**)&Alo_p, g_Alo);
    cudaGetSymbolAddress((void**)&Whi_p, g_Whi);
    cudaGetSymbolAddress((void**)&Wlo_p, g_Wlo);
    cudaGetSymbolAddress((void**)&Q_p, g_Q);
    cudaGetSymbolAddress((void**)&K_p, g_K);
    cudaGetSymbolAddress((void**)&V_p, g_V);
    cudaGetSymbolAddress((void**)&O_p, g_O);

    // 1) split emb and weights to bf16 hi/lo
    split_kernel<<<(MTOT * EE / 4) / 256, 256>>>(emb, Ahi_p, Alo_p);
    split_w_kernel<<<dim3((EE * HD / 4) / 256, 4), 256>>>(Wq, Wk, Wv, Wu);

    // 2) QKV projections on tensor cores (bf16x3, mma.sync)
    mma_gemm_kernel<<<dim3(HD / 128, MTOT / 128, 3), 256, GEMM_SMEM>>>(
        Ahi_p, Alo_p, Whi_p, Wlo_p, Q_p, K_p, V_p, nullptr, nullptr);

    // 3) Per-head LayerNorm on Q (with 1/8 scale) and K
    ln_kernel<<<(2 * MTOT * HH) / 8, 256>>>(qn_w, qn_b, kn_w, kn_b);

    // 4) Attention (fp32)
    attn_kernel<<<dim3(SS / 128, BB * HH), 256, ATTN_SMEM>>>();

    // 5) split attention output, out projection + bias + residual
    split_kernel<<<(MTOT * HD / 4) / 256, 256>>>(O_p, Ahi_p, Alo_p);
    mma_gemm_kernel<<<dim3(EE / 128, MTOT / 128, 1), 256, GEMM_SMEM>>>(
        Ahi_p, Alo_p, Whi_p + (size_t)3 * EE * HD, Wlo_p + (size_t)3 * EE * HD,
        out, nullptr, nullptr, emb, bu);
}

// round 5
// speedup vs baseline: 3.5928x; 2.6735x over previous
#include <cuda_runtime.h>
#include <cuda_bf16.h>
#include <cstdint>

#define BB 2
#define SS 2048
#define EE 1024
#define HH 16
#define DD 64
#define MTOT (BB*SS)    // 4096
#define HD (HH*DD)      // 1024

// fp32 scratch (QKV projection outputs)
__device__ float g_Q[(size_t)MTOT * HD];
__device__ float g_K[(size_t)MTOT * HD];
__device__ float g_V[(size_t)MTOT * HD];
// bf16 operands for attention
__device__ __nv_bfloat16 g_Qh[(size_t)MTOT * HD];
__device__ __nv_bfloat16 g_Kh[(size_t)MTOT * HD];
__device__ __nv_bfloat16 g_Vh[(size_t)MTOT * HD];
// bf16 split scratch (A operand: emb for QKV gemm, then attention output)
__device__ __nv_bfloat16 g_Ahi[(size_t)MTOT * HD];
__device__ __nv_bfloat16 g_Alo[(size_t)MTOT * HD];
// weights hi/lo: Wq @0, Wk @1M, Wv @2M, Wu @3M
__device__ __nv_bfloat16 g_Whi[(size_t)4 * EE * HD];
__device__ __nv_bfloat16 g_Wlo[(size_t)4 * EE * HD];

// ===========================================================================
// helpers (arch-portable: cp.async + ldmatrix + mma.sync, sm_80+ PTX)
// ===========================================================================
__device__ __forceinline__ uint32_t smem_to_u32(const void* p) {
    uint32_t a;
    asm("{ .reg .u64 t; cvta.to.shared.u64 t, %1; cvt.u32.u64 %0, t; }"
        : "=r"(a) : "l"(p));
    return a;
}
__device__ __forceinline__ void cp16(uint32_t d, const void* s) {
    asm volatile("cp.async.ca.shared.global [%0], [%1], 16;" :: "r"(d), "l"(s));
}
__device__ __forceinline__ void cp_commit() {
    asm volatile("cp.async.commit_group;" ::: "memory");
}
template <int N>
__device__ __forceinline__ void cp_wait() {
    asm volatile("cp.async.wait_group %0;" :: "n"(N) : "memory");
}
__device__ __forceinline__ void ldm_x4(uint32_t* r, uint32_t addr) {
    asm volatile("ldmatrix.sync.aligned.m8n8.x4.shared.b16 {%0,%1,%2,%3}, [%4];"
        : "=r"(r[0]), "=r"(r[1]), "=r"(r[2]), "=r"(r[3]) : "r"(addr));
}
__device__ __forceinline__ void ldm_x4_t(uint32_t* r, uint32_t addr) {
    asm volatile("ldmatrix.sync.aligned.m8n8.x4.trans.shared.b16 {%0,%1,%2,%3}, [%4];"
        : "=r"(r[0]), "=r"(r[1]), "=r"(r[2]), "=r"(r[3]) : "r"(addr));
}
__device__ __forceinline__ void mma_bf16(float* d, const uint32_t* a, const uint32_t* b) {
    asm volatile(
        "mma.sync.aligned.m16n8k16.row.col.f32.bf16.bf16.f32 "
        "{%0,%1,%2,%3}, {%4,%5,%6,%7}, {%8,%9}, {%0,%1,%2,%3};"
        : "+f"(d[0]), "+f"(d[1]), "+f"(d[2]), "+f"(d[3])
        : "r"(a[0]), "r"(a[1]), "r"(a[2]), "r"(a[3]), "r"(b[0]), "r"(b[1]));
}
// 2^y via bit-trick round + degree-5 poly. y <= ~0 expected; clamped.
__device__ __forceinline__ float exp2_poly(float y) {
    y = fmaxf(y, -100.0f);
    float t = y + 12582912.0f;                 // 1.5*2^23: round-to-nearest
    int ibits = __float_as_int(t) << 23;       // i << 23 (mod 2^32)
    float f = y - (t - 12582912.0f);           // f in [-0.5, 0.5]
    float p = 1.3333558146e-3f;
    p = fmaf(p, f, 9.6181291076e-3f);
    p = fmaf(p, f, 5.5504108664e-2f);
    p = fmaf(p, f, 2.4022650696e-1f);
    p = fmaf(p, f, 6.9314718056e-1f);
    p = fmaf(p, f, 1.0f);
    return __int_as_float(__float_as_int(p) + ibits);
}

// ===========================================================================
// bf16 split conversion kernels
// ===========================================================================
__global__ __launch_bounds__(256) void split_kernel(
    const float* __restrict__ src, __nv_bfloat16* __restrict__ hi,
    __nv_bfloat16* __restrict__ lo)
{
    int i = blockIdx.x * blockDim.x + threadIdx.x;
    float4 v = ((const float4*)src)[i];
    __nv_bfloat16 h0 = __float2bfloat16(v.x);
    __nv_bfloat16 h1 = __float2bfloat16(v.y);
    __nv_bfloat16 h2 = __float2bfloat16(v.z);
    __nv_bfloat16 h3 = __float2bfloat16(v.w);
    __nv_bfloat16 l0 = __float2bfloat16(v.x - __bfloat162float(h0));
    __nv_bfloat16 l1 = __float2bfloat16(v.y - __bfloat162float(h1));
    __nv_bfloat16 l2 = __float2bfloat16(v.z - __bfloat162float(h2));
    __nv_bfloat16 l3 = __float2bfloat16(v.w - __bfloat162float(h3));
    ((__nv_bfloat162*)hi)[2 * i + 0] = __halves2bfloat162(h0, h1);
    ((__nv_bfloat162*)hi)[2 * i + 1] = __halves2bfloat162(h2, h3);
    ((__nv_bfloat162*)lo)[2 * i + 0] = __halves2bfloat162(l0, l1);
    ((__nv_bfloat162*)lo)[2 * i + 1] = __halves2bfloat162(l2, l3);
}

__global__ __launch_bounds__(256) void split_w_kernel(
    const float* __restrict__ Wq, const float* __restrict__ Wk,
    const float* __restrict__ Wv, const float* __restrict__ Wu)
{
    int z = blockIdx.y;
    const float* src = (z == 0) ? Wq : (z == 1) ? Wk : (z == 2) ? Wv : Wu;
    size_t base = (size_t)z * EE * HD;
    int i = blockIdx.x * blockDim.x + threadIdx.x;
    float4 v = ((const float4*)src)[i];
    __nv_bfloat16 h0 = __float2bfloat16(v.x);
    __nv_bfloat16 h1 = __float2bfloat16(v.y);
    __nv_bfloat16 h2 = __float2bfloat16(v.z);
    __nv_bfloat16 h3 = __float2bfloat16(v.w);
    __nv_bfloat16 l0 = __float2bfloat16(v.x - __bfloat162float(h0));
    __nv_bfloat16 l1 = __float2bfloat16(v.y - __bfloat162float(h1));
    __nv_bfloat16 l2 = __float2bfloat16(v.z - __bfloat162float(h2));
    __nv_bfloat16 l3 = __float2bfloat16(v.w - __bfloat162float(h3));
    ((__nv_bfloat162*)(g_Whi + base))[2 * i + 0] = __halves2bfloat162(h0, h1);
    ((__nv_bfloat162*)(g_Whi + base))[2 * i + 1] = __halves2bfloat162(h2, h3);
    ((__nv_bfloat162*)(g_Wlo + base))[2 * i + 0] = __halves2bfloat162(l0, l1);
    ((__nv_bfloat162*)(g_Wlo + base))[2 * i + 1] = __halves2bfloat162(l2, l3);
}

// V fp32 -> bf16 (single)
__global__ __launch_bounds__(256) void vconv_kernel()
{
    int i = blockIdx.x * blockDim.x + threadIdx.x;   // over MTOT*HD/8
    float4 a = ((const float4*)g_V)[2 * i + 0];
    float4 b = ((const float4*)g_V)[2 * i + 1];
    __nv_bfloat162* dst = (__nv_bfloat162*)g_Vh + 4 * i;
    dst[0] = __halves2bfloat162(__float2bfloat16(a.x), __float2bfloat16(a.y));
    dst[1] = __halves2bfloat162(__float2bfloat16(a.z), __float2bfloat16(a.w));
    dst[2] = __halves2bfloat162(__float2bfloat16(b.x), __float2bfloat16(b.y));
    dst[3] = __halves2bfloat162(__float2bfloat16(b.z), __float2bfloat16(b.w));
}

// ===========================================================================
// bf16x3 mma.sync GEMM (unchanged from R4, validated 5e-7)
// ===========================================================================
#define ASTR 40
#define TILE_BYTES (128 * ASTR * 2)
#define STAGE_BYTES (4 * TILE_BYTES)
#define GEMM_SMEM (2 * STAGE_BYTES)

__global__ __launch_bounds__(256, 1) void mma_gemm_kernel(
    const __nv_bfloat16* __restrict__ Ahi, const __nv_bfloat16* __restrict__ Alo,
    const __nv_bfloat16* __restrict__ Bhi_all, const __nv_bfloat16* __restrict__ Blo_all,
    float* C0, float* C1, float* C2,
    const float* __restrict__ emb, const float* __restrict__ bu)
{
    extern __shared__ char smem[];
    const uint32_t sb = smem_to_u32(smem);
    const int tid = threadIdx.x;
    const int wid = tid >> 5, lane = tid & 31;
    const int bn = blockIdx.x * 128;
    const int bm = blockIdx.y * 128;
    const int z = blockIdx.z;

    const __nv_bfloat16* Bhi = Bhi_all + (size_t)z * EE * HD;
    const __nv_bfloat16* Blo = Blo_all + (size_t)z * EE * HD;
    float* C = (z == 0) ? C0 : (z == 1) ? C1 : C2;

    const int wm = wid & 3;
    const int wn = wid >> 2;

    float acc[2][8][4];
#pragma unroll
    for (int mt = 0; mt < 2; mt++)
#pragma unroll
        for (int nt = 0; nt < 8; nt++)
#pragma unroll
            for (int e = 0; e < 4; e++) acc[mt][nt][e] = 0.0f;

#define LOAD_STAGE(st, kt) do { \
    _Pragma("unroll") \
    for (int it = 0; it < 8; it++) { \
        int idx = tid + it * 256; \
        int tile = idx >> 9, rem = idx & 511, row = rem >> 2, seg = rem & 3; \
        const __nv_bfloat16* srcp = (tile == 0) ? Ahi : (tile == 1) ? Alo \
                                   : (tile == 2) ? Bhi : Blo; \
        int grow = ((tile < 2) ? bm : bn) + row; \
        uint32_t dst = sb + (st) * STAGE_BYTES + tile * TILE_BYTES \
                       + (uint32_t)(row * ASTR + seg * 8) * 2; \
        cp16(dst, srcp + (size_t)grow * 1024 + (kt) + seg * 8); \
    } \
    cp_commit(); \
} while (0)

    LOAD_STAGE(0, 0);

    for (int ch = 0; ch < 32; ch++) {
        if (ch < 31) { LOAD_STAGE((ch + 1) & 1, (ch + 1) * 32); cp_wait<1>(); }
        else         { cp_wait<0>(); }
        __syncthreads();

        const uint32_t base = sb + (ch & 1) * STAGE_BYTES;
        const uint32_t aAh = base;
        const uint32_t aAl = base + TILE_BYTES;
        const uint32_t aBh = base + 2 * TILE_BYTES;
        const uint32_t aBl = base + 3 * TILE_BYTES;

#pragma unroll
        for (int kk = 0; kk < 2; kk++) {
            const int k0 = kk * 16;
            uint32_t ah[2][4], al[2][4], bh[8][2], bl[8][2];
#pragma unroll
            for (int mt = 0; mt < 2; mt++) {
                int mrow = wm * 32 + mt * 16 + ((lane >> 3) & 1) * 8 + (lane & 7);
                int mcol = k0 + (lane >> 4) * 8;
                uint32_t off = (uint32_t)(mrow * ASTR + mcol) * 2;
                ldm_x4(ah[mt], aAh + off);
                ldm_x4(al[mt], aAl + off);
            }
#pragma unroll
            for (int np = 0; np < 4; np++) {
                int nrow = wn * 64 + np * 16 + (lane >> 4) * 8 + (lane & 7);
                int ncol = k0 + ((lane >> 3) & 1) * 8;
                uint32_t off = (uint32_t)(nrow * ASTR + ncol) * 2;
                uint32_t r[4];
                ldm_x4(r, aBh + off);
                bh[np * 2][0] = r[0]; bh[np * 2][1] = r[1];
                bh[np * 2 + 1][0] = r[2]; bh[np * 2 + 1][1] = r[3];
                ldm_x4(r, aBl + off);
                bl[np * 2][0] = r[0]; bl[np * 2][1] = r[1];
                bl[np * 2 + 1][0] = r[2]; bl[np * 2 + 1][1] = r[3];
            }
#pragma unroll
            for (int mt = 0; mt < 2; mt++)
#pragma unroll
                for (int nt = 0; nt < 8; nt++) mma_bf16(acc[mt][nt], ah[mt], bh[nt]);
#pragma unroll
            for (int mt = 0; mt < 2; mt++)
#pragma unroll
                for (int nt = 0; nt < 8; nt++) mma_bf16(acc[mt][nt], ah[mt], bl[nt]);
#pragma unroll
            for (int mt = 0; mt < 2; mt++)
#pragma unroll
                for (int nt = 0; nt < 8; nt++) mma_bf16(acc[mt][nt], al[mt], bh[nt]);
        }
        __syncthreads();
    }

    const int tig = lane & 3, gid = lane >> 2;
#pragma unroll
    for (int mt = 0; mt < 2; mt++) {
        int r0 = bm + wm * 32 + mt * 16 + gid;
#pragma unroll
        for (int nt = 0; nt < 8; nt++) {
            int n = bn + wn * 64 + nt * 8 + tig * 2;
            float2 v0 = make_float2(acc[mt][nt][0], acc[mt][nt][1]);
            float2 v1 = make_float2(acc[mt][nt][2], acc[mt][nt][3]);
            if (emb) {
                float b0 = bu[n], b1 = bu[n + 1];
                float2 e0 = *(const float2*)(emb + (size_t)r0 * EE + n);
                float2 e1 = *(const float2*)(emb + (size_t)(r0 + 8) * EE + n);
                v0.x += b0 + e0.x; v0.y += b1 + e0.y;
                v1.x += b0 + e1.x; v1.y += b1 + e1.y;
            }
            *(float2*)(C + (size_t)r0 * 1024 + n) = v0;
            *(float2*)(C + (size_t)(r0 + 8) * 1024 + n) = v1;
        }
    }
}

// ---------------------------------------------------------------------------
// LayerNorm over D=64 per (tensor,row,head). One warp per task.
// Writes bf16 directly. Q folded by 0.125*log2(e) (scores land in log2 units).
// ---------------------------------------------------------------------------
__global__ __launch_bounds__(256) void ln_kernel(
    const float* __restrict__ qw, const float* __restrict__ qb,
    const float* __restrict__ kw, const float* __restrict__ kb)
{
    int warp = (blockIdx.x * blockDim.x + threadIdx.x) >> 5;
    int lane = threadIdx.x & 31;
    int tensor = warp >> 16;
    int rem = warp & 65535;
    int row = rem >> 4;
    int head = rem & 15;

    const float* p = (tensor ? g_K : g_Q) + (size_t)row * HD + head * DD;
    __nv_bfloat16* po = (tensor ? g_Kh : g_Qh) + (size_t)row * HD + head * DD;
    const float* w = tensor ? kw : qw;
    const float* bb = tensor ? kb : qb;
    const float scale = tensor ? 1.0f : 0.1803368801111243f;  // 0.125*log2(e)

    float x0 = p[lane];
    float x1 = p[lane + 32];
    float s = x0 + x1;
    float sq = x0 * x0 + x1 * x1;
#pragma unroll
    for (int o = 16; o > 0; o >>= 1) {
        s  += __shfl_xor_sync(0xffffffffu, s, o);
        sq += __shfl_xor_sync(0xffffffffu, sq, o);
    }
    float mean = s * (1.0f / 64.0f);
    float var = sq * (1.0f / 64.0f) - mean * mean;
    float inv = rsqrtf(var + 1e-5f);
    po[lane]      = __float2bfloat16(((x0 - mean) * inv * w[lane]      + bb[lane])      * scale);
    po[lane + 32] = __float2bfloat16(((x1 - mean) * inv * w[lane + 32] + bb[lane + 32]) * scale);
}

// ---------------------------------------------------------------------------
// Flash attention on mma.sync (bf16). grid (S/128, B*H), 256 threads (8 warps).
// Warp = 16 q rows. KV tile 128. Scores in log2 units (scale folded into Q).
// Output written as bf16 hi/lo into g_Ahi/g_Alo for the out-projection GEMM.
// ---------------------------------------------------------------------------
#define QSTR 72                         // bf16 per smem row (144 B)
#define ATILE (128 * QSTR * 2)          // 18432 bytes per 128x64 tile
#define KV_OFF ATILE                    // Q at 0
#define KVSTAGE (2 * ATILE)             // K + V
#define ATTN_SMEM (ATILE + 2 * KVSTAGE) // 92160

__global__ __launch_bounds__(256, 1) void attn_kernel()
{
    extern __shared__ char smem[];
    const uint32_t sb = smem_to_u32(smem);
    const int tid = threadIdx.x;
    const int wid = tid >> 5, lane = tid & 31;
    const int gid = lane >> 2, tig = lane & 3;
    const int q0 = blockIdx.x * 128;
    const int bh = blockIdx.y;
    const int b = bh >> 4, h = bh & 15;

    const __nv_bfloat16* Qg = g_Qh + (size_t)(b * SS + q0) * HD + h * DD;
    const __nv_bfloat16* Kg = g_Kh + (size_t)(b * SS) * HD + h * DD;
    const __nv_bfloat16* Vg = g_Vh + (size_t)(b * SS) * HD + h * DD;

    // load Q tile: 1024 chunks of 16B
#pragma unroll
    for (int p = 0; p < 4; p++) {
        int idx = tid + p * 256;
        int row = idx >> 3, seg = idx & 7;
        cp16(sb + (uint32_t)(row * QSTR + seg * 8) * 2,
             Qg + (size_t)row * HD + seg * 8);
    }
    cp_commit();

#define LOAD_KV(st, it) do { \
    int kvb = (it) * 128; \
    _Pragma("unroll") \
    for (int p = 0; p < 8; p++) { \
        int idx = tid + p * 256; \
        int tile = idx >> 10, row = (idx >> 3) & 127, seg = idx & 7; \
        const __nv_bfloat16* src = tile ? Vg : Kg; \
        uint32_t dst = sb + KV_OFF + (st) * KVSTAGE + tile * ATILE \
                       + (uint32_t)(row * QSTR + seg * 8) * 2; \
        cp16(dst, src + (size_t)(kvb + row) * HD + seg * 8); \
    } \
    cp_commit(); \
} while (0)

    LOAD_KV(0, 0);
    cp_wait<1>();          // Q done (KV0 may be pending)
    __syncthreads();

    // Q a-fragments (resident): 4 k-steps
    uint32_t qf[4][4];
#pragma unroll
    for (int kk = 0; kk < 4; kk++) {
        int mrow = wid * 16 + ((lane >> 3) & 1) * 8 + (lane & 7);
        int mcol = kk * 16 + (lane >> 4) * 8;
        ldm_x4(qf[kk], sb + (uint32_t)(mrow * QSTR + mcol) * 2);
    }

    float o[8][4];
#pragma unroll
    for (int nt = 0; nt < 8; nt++)
#pragma unroll
        for (int e = 0; e < 4; e++) o[nt][e] = 0.0f;
    float m0 = -1e30f, m1 = -1e30f, l0 = 0.0f, l1 = 0.0f;

    for (int it = 0; it < 16; it++) {
        if (it < 15) { LOAD_KV((it + 1) & 1, it + 1); cp_wait<1>(); }
        else         { cp_wait<0>(); }
        __syncthreads();

        const uint32_t Kb = sb + KV_OFF + (it & 1) * KVSTAGE;
        const uint32_t Vb = Kb + ATILE;

        // S = Q K^T  (128 kv cols per warp-row-block, 16 n-tiles)
        float s[16][4];
#pragma unroll
        for (int nt = 0; nt < 16; nt++)
#pragma unroll
            for (int e = 0; e < 4; e++) s[nt][e] = 0.0f;

#pragma unroll
        for (int kk = 0; kk < 4; kk++) {
#pragma unroll
            for (int np = 0; np < 8; np++) {
                int nrow = np * 16 + (lane >> 4) * 8 + (lane & 7);
                int ncol = kk * 16 + ((lane >> 3) & 1) * 8;
                uint32_t r[4];
                ldm_x4(r, Kb + (uint32_t)(nrow * QSTR + ncol) * 2);
                mma_bf16(s[np * 2],     qf[kk], r);
                mma_bf16(s[np * 2 + 1], qf[kk], r + 2);
            }
        }

        // online softmax (scores already in log2 units)
        float mx0 = s[0][0], mx1 = s[0][2];
#pragma unroll
        for (int nt = 0; nt < 16; nt++) {
            mx0 = fmaxf(mx0, fmaxf(s[nt][0], s[nt][1]));
            mx1 = fmaxf(mx1, fmaxf(s[nt][2], s[nt][3]));
        }
        mx0 = fmaxf(mx0, __shfl_xor_sync(0xffffffffu, mx0, 1));
        mx0 = fmaxf(mx0, __shfl_xor_sync(0xffffffffu, mx0, 2));
        mx1 = fmaxf(mx1, __shfl_xor_sync(0xffffffffu, mx1, 1));
        mx1 = fmaxf(mx1, __shfl_xor_sync(0xffffffffu, mx1, 2));
        float mn0 = fmaxf(m0, mx0), mn1 = fmaxf(m1, mx1);
        float al0 = exp2_poly(m0 - mn0), al1 = exp2_poly(m1 - mn1);
        m0 = mn0; m1 = mn1;

        float rs0 = 0.0f, rs1 = 0.0f;
#pragma unroll
        for (int nt = 0; nt < 16; nt++) {
            s[nt][0] = exp2_poly(s[nt][0] - mn0); rs0 += s[nt][0];
            s[nt][1] = exp2_poly(s[nt][1] - mn0); rs0 += s[nt][1];
            s[nt][2] = exp2_poly(s[nt][2] - mn1); rs1 += s[nt][2];
            s[nt][3] = exp2_poly(s[nt][3] - mn1); rs1 += s[nt][3];
        }
        rs0 += __shfl_xor_sync(0xffffffffu, rs0, 1);
        rs0 += __shfl_xor_sync(0xffffffffu, rs0, 2);
        rs1 += __shfl_xor_sync(0xffffffffu, rs1, 1);
        rs1 += __shfl_xor_sync(0xffffffffu, rs1, 2);
        l0 = l0 * al0 + rs0;
        l1 = l1 * al1 + rs1;
#pragma unroll
        for (int nt = 0; nt < 8; nt++) {
            o[nt][0] *= al0; o[nt][1] *= al0;
            o[nt][2] *= al1; o[nt][3] *= al1;
        }

        // O += P V   (P from registers; V b-frags via ldmatrix.trans)
#pragma unroll
        for (int t = 0; t < 8; t++) {
            uint32_t pa[4];
            asm("cvt.rn.bf16x2.f32 %0, %1, %2;" : "=r"(pa[0])
                : "f"(s[2 * t][1]), "f"(s[2 * t][0]));
            asm("cvt.rn.bf16x2.f32 %0, %1, %2;" : "=r"(pa[1])
                : "f"(s[2 * t][3]), "f"(s[2 * t][2]));
            asm("cvt.rn.bf16x2.f32 %0, %1, %2;" : "=r"(pa[2])
                : "f"(s[2 * t + 1][1]), "f"(s[2 * t + 1][0]));
            asm("cvt.rn.bf16x2.f32 %0, %1, %2;" : "=r"(pa[3])
                : "f"(s[2 * t + 1][3]), "f"(s[2 * t + 1][2]));
#pragma unroll
            for (int nh = 0; nh < 4; nh++) {
                int kvrow = t * 16 + ((lane >> 3) & 1) * 8 + (lane & 7);
                int col   = nh * 16 + (lane >> 4) * 8;
                uint32_t r[4];
                ldm_x4_t(r, Vb + (uint32_t)(kvrow * QSTR + col) * 2);
                mma_bf16(o[nh * 2],     pa, r);
                mma_bf16(o[nh * 2 + 1], pa, r + 2);
            }
        }
        __syncthreads();
    }

    // epilogue: write O/l as bf16 hi+lo into g_Ahi/g_Alo
    const float rl0 = 1.0f / l0, rl1 = 1.0f / l1;
    const size_t row0 = (size_t)(b * SS + q0 + wid * 16 + gid) * HD;
    const size_t row1 = row0 + 8 * HD;
#pragma unroll
    for (int nt = 0; nt < 8; nt++) {
        int col = h * DD + nt * 8 + 2 * tig;
        float v0 = o[nt][0] * rl0, v1 = o[nt][1] * rl0;
        float v2 = o[nt][2] * rl1, v3 = o[nt][3] * rl1;
        __nv_bfloat16 h0 = __float2bfloat16(v0), h1 = __float2bfloat16(v1);
        __nv_bfloat16 h2 = __float2bfloat16(v2), h3 = __float2bfloat16(v3);
        __nv_bfloat16 e0 = __float2bfloat16(v0 - __bfloat162float(h0));
        __nv_bfloat16 e1 = __float2bfloat16(v1 - __bfloat162float(h1));
        __nv_bfloat16 e2 = __float2bfloat16(v2 - __bfloat162float(h2));
        __nv_bfloat16 e3 = __float2bfloat16(v3 - __bfloat162float(h3));
        *(__nv_bfloat162*)(g_Ahi + row0 + col) = __halves2bfloat162(h0, h1);
        *(__nv_bfloat162*)(g_Alo + row0 + col) = __halves2bfloat162(e0, e1);
        *(__nv_bfloat162*)(g_Ahi + row1 + col) = __halves2bfloat162(h2, h3);
        *(__nv_bfloat162*)(g_Alo + row1 + col) = __halves2bfloat162(e2, e3);
    }
}

// ---------------------------------------------------------------------------
extern "C" void kernel_launch(void* const* d_in, const int* in_sizes, int n_in,
                              void* d_out, int out_size)
{
    const float* emb  = (const float*)d_in[0];
    const float* Wq   = (const float*)d_in[1];
    const float* Wk   = (const float*)d_in[2];
    const float* Wv   = (const float*)d_in[3];
    const float* Wu   = (const float*)d_in[4];
    const float* bu   = (const float*)d_in[5];
    const float* qn_w = (const float*)d_in[6];
    const float* qn_b = (const float*)d_in[7];
    const float* kn_w = (const float*)d_in[8];
    const float* kn_b = (const float*)d_in[9];
    float* out = (float*)d_out;

    (void)in_sizes; (void)n_in; (void)out_size;

    cudaFuncSetAttribute(attn_kernel,
                         cudaFuncAttributeMaxDynamicSharedMemorySize, ATTN_SMEM);
    cudaFuncSetAttribute(mma_gemm_kernel,
                         cudaFuncAttributeMaxDynamicSharedMemorySize, GEMM_SMEM);

    __nv_bfloat16 *Ahi_p, *Alo_p, *Whi_p, *Wlo_p;
    float *Q_p, *K_p, *V_p;
    cudaGetSymbolAddress((void**)&Ahi_p, g_Ahi);
    cudaGetSymbolAddress((void**)&Alo_p, g_Alo);
    cudaGetSymbolAddress((void**)&Whi_p, g_Whi);
    cudaGetSymbolAddress((void**)&Wlo_p, g_Wlo);
    cudaGetSymbolAddress((void**)&Q_p, g_Q);
    cudaGetSymbolAddress((void**)&K_p, g_K);
    cudaGetSymbolAddress((void**)&V_p, g_V);

    // 1) split emb and weights to bf16 hi/lo
    split_kernel<<<(MTOT * EE / 4) / 256, 256>>>(emb, Ahi_p, Alo_p);
    split_w_kernel<<<dim3((EE * HD / 4) / 256, 4), 256>>>(Wq, Wk, Wv, Wu);

    // 2) QKV projections (bf16x3, mma.sync)
    mma_gemm_kernel<<<dim3(HD / 128, MTOT / 128, 3), 256, GEMM_SMEM>>>(
        Ahi_p, Alo_p, Whi_p, Wlo_p, Q_p, K_p, V_p, nullptr, nullptr);

    // 3) LayerNorm -> bf16 Qh (with 0.125*log2e) / Kh
    ln_kernel<<<(2 * MTOT * HH) / 8, 256>>>(qn_w, qn_b, kn_w, kn_b);

    // 4) V -> bf16
    vconv_kernel<<<(MTOT * HD / 8) / 256, 256>>>();

    // 5) Attention (tensor cores + FMA-pipe exp), writes Ahi/Alo
    attn_kernel<<<dim3(SS / 128, BB * HH), 256, ATTN_SMEM>>>();

    // 6) Output projection + bias + residual
    mma_gemm_kernel<<<dim3(EE / 128, MTOT / 128, 1), 256, GEMM_SMEM>>>(
        Ahi_p, Alo_p, Whi_p + (size_t)3 * EE * HD, Wlo_p + (size_t)3 * EE * HD,
        out, nullptr, nullptr, emb, bu);
}

// round 8
// speedup vs baseline: 5.2803x; 1.4697x over previous
#include <cuda_runtime.h>
#include <cuda_bf16.h>
#include <cstdint>

#define BB 2
#define SS 2048
#define EE 1024
#define HH 16
#define DD 64
#define MTOT (BB*SS)    // 4096
#define HD (HH*DD)      // 1024

// fp32 scratch (Q/K projection outputs, pre-LN)
__device__ float g_Q[(size_t)MTOT * HD];
__device__ float g_K[(size_t)MTOT * HD];
// bf16 operands
__device__ __nv_bfloat16 g_Qh[(size_t)MTOT * HD];
__device__ __nv_bfloat16 g_Kh[(size_t)MTOT * HD];
__device__ __nv_bfloat16 g_Vh[(size_t)MTOT * HD];
__device__ __nv_bfloat16 g_EmbH[(size_t)MTOT * HD];   // emb bf16 (QKV A operand)
__device__ __nv_bfloat16 g_AttnH[(size_t)MTOT * HD];  // attn out bf16 (out-proj A)
// weights bf16: Wq @0, Wk @1M, Wv @2M, Wu @3M
__device__ __nv_bfloat16 g_Wh[(size_t)4 * EE * HD];

// ===========================================================================
// helpers (arch-portable: cp.async + ldmatrix + mma.sync, sm_80+ PTX)
// ===========================================================================
__device__ __forceinline__ uint32_t smem_to_u32(const void* p) {
    uint32_t a;
    asm("{ .reg .u64 t; cvta.to.shared.u64 t, %1; cvt.u32.u64 %0, t; }"
        : "=r"(a) : "l"(p));
    return a;
}
__device__ __forceinline__ void cp16(uint32_t d, const void* s) {
    asm volatile("cp.async.ca.shared.global [%0], [%1], 16;" :: "r"(d), "l"(s));
}
__device__ __forceinline__ void cp_commit() {
    asm volatile("cp.async.commit_group;" ::: "memory");
}
template <int N>
__device__ __forceinline__ void cp_wait() {
    asm volatile("cp.async.wait_group %0;" :: "n"(N) : "memory");
}
__device__ __forceinline__ void ldm_x4(uint32_t* r, uint32_t addr) {
    asm volatile("ldmatrix.sync.aligned.m8n8.x4.shared.b16 {%0,%1,%2,%3}, [%4];"
        : "=r"(r[0]), "=r"(r[1]), "=r"(r[2]), "=r"(r[3]) : "r"(addr));
}
__device__ __forceinline__ void ldm_x4_t(uint32_t* r, uint32_t addr) {
    asm volatile("ldmatrix.sync.aligned.m8n8.x4.trans.shared.b16 {%0,%1,%2,%3}, [%4];"
        : "=r"(r[0]), "=r"(r[1]), "=r"(r[2]), "=r"(r[3]) : "r"(addr));
}
__device__ __forceinline__ void mma_bf16(float* d, const uint32_t* a, const uint32_t* b) {
    asm volatile(
        "mma.sync.aligned.m16n8k16.row.col.f32.bf16.bf16.f32 "
        "{%0,%1,%2,%3}, {%4,%5,%6,%7}, {%8,%9}, {%0,%1,%2,%3};"
        : "+f"(d[0]), "+f"(d[1]), "+f"(d[2]), "+f"(d[3])
        : "r"(a[0]), "r"(a[1]), "r"(a[2]), "r"(a[3]), "r"(b[0]), "r"(b[1]));
}
// 2^y via bit-trick round + degree-5 poly (FMA pipe only).
__device__ __forceinline__ float exp2_poly(float y) {
    y = fmaxf(y, -100.0f);
    float t = y + 12582912.0f;
    int ibits = __float_as_int(t) << 23;
    float f = y - (t - 12582912.0f);
    float p = 1.3333558146e-3f;
    p = fmaf(p, f, 9.6181291076e-3f);
    p = fmaf(p, f, 5.5504108664e-2f);
    p = fmaf(p, f, 2.4022650696e-1f);
    p = fmaf(p, f, 6.9314718056e-1f);
    p = fmaf(p, f, 1.0f);
    return __int_as_float(__float_as_int(p) + ibits);
}

// ===========================================================================
// fp32 -> bf16 conversion kernels
// ===========================================================================
__global__ __launch_bounds__(256) void conv_kernel(
    const float* __restrict__ src, __nv_bfloat16* __restrict__ dst)
{
    int i = blockIdx.x * blockDim.x + threadIdx.x;   // over n/8
    float4 a = ((const float4*)src)[2 * i + 0];
    float4 b = ((const float4*)src)[2 * i + 1];
    __nv_bfloat162* d = (__nv_bfloat162*)dst + 4 * i;
    d[0] = __halves2bfloat162(__float2bfloat16(a.x), __float2bfloat16(a.y));
    d[1] = __halves2bfloat162(__float2bfloat16(a.z), __float2bfloat16(a.w));
    d[2] = __halves2bfloat162(__float2bfloat16(b.x), __float2bfloat16(b.y));
    d[3] = __halves2bfloat162(__float2bfloat16(b.z), __float2bfloat16(b.w));
}

__global__ __launch_bounds__(256) void conv_w_kernel(
    const float* __restrict__ Wq, const float* __restrict__ Wk,
    const float* __restrict__ Wv, const float* __restrict__ Wu)
{
    int z = blockIdx.y;
    const float* src = (z == 0) ? Wq : (z == 1) ? Wk : (z == 2) ? Wv : Wu;
    size_t base = (size_t)z * EE * HD;
    int i = blockIdx.x * blockDim.x + threadIdx.x;   // over 1M/8
    float4 a = ((const float4*)src)[2 * i + 0];
    float4 b = ((const float4*)src)[2 * i + 1];
    __nv_bfloat162* d = (__nv_bfloat162*)(g_Wh + base) + 4 * i;
    d[0] = __halves2bfloat162(__float2bfloat16(a.x), __float2bfloat16(a.y));
    d[1] = __halves2bfloat162(__float2bfloat16(a.z), __float2bfloat16(a.w));
    d[2] = __halves2bfloat162(__float2bfloat16(b.x), __float2bfloat16(b.y));
    d[3] = __halves2bfloat162(__float2bfloat16(b.z), __float2bfloat16(b.w));
}

// ===========================================================================
// bf16 single-product mma.sync GEMM: C[m,n] = sum_k A[m,k]*B[n,k]
// Block 128x128, BK=32, 8 warps (warp tile 32x64), cp.async double buffer.
// z==2 writes bf16 to g_Vh; else fp32 to C0/C1 (+ optional emb/bu epilogue).
// ===========================================================================
#define ASTR 40
#define TILE_BYTES (128 * ASTR * 2)       // 10240
#define STAGE_BYTES (2 * TILE_BYTES)      // 20480
#define GEMM_SMEM (2 * STAGE_BYTES)       // 40960

__global__ __launch_bounds__(256, 1) void mma_gemm_kernel(
    const __nv_bfloat16* __restrict__ A,
    const __nv_bfloat16* __restrict__ Wall,
    float* C0, float* C1,
    const float* __restrict__ emb, const float* __restrict__ bu)
{
    extern __shared__ char smem[];
    const uint32_t sb = smem_to_u32(smem);
    const int tid = threadIdx.x;
    const int wid = tid >> 5, lane = tid & 31;
    const int bn = blockIdx.x * 128;
    const int bm = blockIdx.y * 128;
    const int z = blockIdx.z;

    const __nv_bfloat16* Bp = Wall + (size_t)z * EE * HD;
    const int wm = wid & 3;
    const int wn = wid >> 2;

    float acc[2][8][4];
#pragma unroll
    for (int mt = 0; mt < 2; mt++)
#pragma unroll
        for (int nt = 0; nt < 8; nt++)
#pragma unroll
            for (int e = 0; e < 4; e++) acc[mt][nt][e] = 0.0f;

#define LOAD_STAGE(st, kt) do { \
    _Pragma("unroll") \
    for (int it = 0; it < 4; it++) { \
        int idx = tid + it * 256; \
        int tile = idx >> 9, rem = idx & 511, row = rem >> 2, seg = rem & 3; \
        const __nv_bfloat16* srcp = tile ? Bp : A; \
        int grow = (tile ? bn : bm) + row; \
        uint32_t dst = sb + (st) * STAGE_BYTES + tile * TILE_BYTES \
                       + (uint32_t)(row * ASTR + seg * 8) * 2; \
        cp16(dst, srcp + (size_t)grow * 1024 + (kt) + seg * 8); \
    } \
    cp_commit(); \
} while (0)

    LOAD_STAGE(0, 0);

    for (int ch = 0; ch < 32; ch++) {
        if (ch < 31) { LOAD_STAGE((ch + 1) & 1, (ch + 1) * 32); cp_wait<1>(); }
        else         { cp_wait<0>(); }
        __syncthreads();

        const uint32_t aA = sb + (ch & 1) * STAGE_BYTES;
        const uint32_t aB = aA + TILE_BYTES;

#pragma unroll
        for (int kk = 0; kk < 2; kk++) {
            const int k0 = kk * 16;
            uint32_t ah[2][4], bh[8][2];
#pragma unroll
            for (int mt = 0; mt < 2; mt++) {
                int mrow = wm * 32 + mt * 16 + ((lane >> 3) & 1) * 8 + (lane & 7);
                int mcol = k0 + (lane >> 4) * 8;
                ldm_x4(ah[mt], aA + (uint32_t)(mrow * ASTR + mcol) * 2);
            }
#pragma unroll
            for (int np = 0; np < 4; np++) {
                int nrow = wn * 64 + np * 16 + (lane >> 4) * 8 + (lane & 7);
                int ncol = k0 + ((lane >> 3) & 1) * 8;
                uint32_t r[4];
                ldm_x4(r, aB + (uint32_t)(nrow * ASTR + ncol) * 2);
                bh[np * 2][0] = r[0]; bh[np * 2][1] = r[1];
                bh[np * 2 + 1][0] = r[2]; bh[np * 2 + 1][1] = r[3];
            }
#pragma unroll
            for (int mt = 0; mt < 2; mt++)
#pragma unroll
                for (int nt = 0; nt < 8; nt++) mma_bf16(acc[mt][nt], ah[mt], bh[nt]);
        }
        __syncthreads();
    }

    const int tig = lane & 3, gid = lane >> 2;
    if (z == 2) {
        // V: write bf16 directly
#pragma unroll
        for (int mt = 0; mt < 2; mt++) {
            int r0 = bm + wm * 32 + mt * 16 + gid;
#pragma unroll
            for (int nt = 0; nt < 8; nt++) {
                int n = bn + wn * 64 + nt * 8 + tig * 2;
                *(__nv_bfloat162*)(g_Vh + (size_t)r0 * HD + n) =
                    __halves2bfloat162(__float2bfloat16(acc[mt][nt][0]),
                                       __float2bfloat16(acc[mt][nt][1]));
                *(__nv_bfloat162*)(g_Vh + (size_t)(r0 + 8) * HD + n) =
                    __halves2bfloat162(__float2bfloat16(acc[mt][nt][2]),
                                       __float2bfloat16(acc[mt][nt][3]));
            }
        }
    } else {
        float* C = (z == 0) ? C0 : C1;
#pragma unroll
        for (int mt = 0; mt < 2; mt++) {
            int r0 = bm + wm * 32 + mt * 16 + gid;
#pragma unroll
            for (int nt = 0; nt < 8; nt++) {
                int n = bn + wn * 64 + nt * 8 + tig * 2;
                float2 v0 = make_float2(acc[mt][nt][0], acc[mt][nt][1]);
                float2 v1 = make_float2(acc[mt][nt][2], acc[mt][nt][3]);
                if (emb) {
                    float b0 = bu[n], b1 = bu[n + 1];
                    float2 e0 = *(const float2*)(emb + (size_t)r0 * EE + n);
                    float2 e1 = *(const float2*)(emb + (size_t)(r0 + 8) * EE + n);
                    v0.x += b0 + e0.x; v0.y += b1 + e0.y;
                    v1.x += b0 + e1.x; v1.y += b1 + e1.y;
                }
                *(float2*)(C + (size_t)r0 * 1024 + n) = v0;
                *(float2*)(C + (size_t)(r0 + 8) * 1024 + n) = v1;
            }
        }
    }
}

// ---------------------------------------------------------------------------
// LayerNorm over D=64 per (tensor,row,head). One warp per task.
// Writes bf16. Q folded by 0.125*log2(e) (scores land in log2 units).
// ---------------------------------------------------------------------------
__global__ __launch_bounds__(256) void ln_kernel(
    const float* __restrict__ qw, const float* __restrict__ qb,
    const float* __restrict__ kw, const float* __restrict__ kb)
{
    int warp = (blockIdx.x * blockDim.x + threadIdx.x) >> 5;
    int lane = threadIdx.x & 31;
    int tensor = warp >> 16;
    int rem = warp & 65535;
    int row = rem >> 4;
    int head = rem & 15;

    const float* p = (tensor ? g_K : g_Q) + (size_t)row * HD + head * DD;
    __nv_bfloat16* po = (tensor ? g_Kh : g_Qh) + (size_t)row * HD + head * DD;
    const float* w = tensor ? kw : qw;
    const float* bb = tensor ? kb : qb;
    const float scale = tensor ? 1.0f : 0.1803368801111243f;  // 0.125*log2(e)

    float x0 = p[lane];
    float x1 = p[lane + 32];
    float s = x0 + x1;
    float sq = x0 * x0 + x1 * x1;
#pragma unroll
    for (int o = 16; o > 0; o >>= 1) {
        s  += __shfl_xor_sync(0xffffffffu, s, o);
        sq += __shfl_xor_sync(0xffffffffu, sq, o);
    }
    float mean = s * (1.0f / 64.0f);
    float var = sq * (1.0f / 64.0f) - mean * mean;
    float inv = rsqrtf(var + 1e-5f);
    po[lane]      = __float2bfloat16(((x0 - mean) * inv * w[lane]      + bb[lane])      * scale);
    po[lane + 32] = __float2bfloat16(((x1 - mean) * inv * w[lane + 32] + bb[lane + 32]) * scale);
}

// ---------------------------------------------------------------------------
// Flash attention on mma.sync (bf16). grid (S/128, B*H), 256 threads (8 warps).
// Warp = 16 q rows. KV tile 128. Scores in log2 units.
// Output written as bf16 into g_AttnH.
// ---------------------------------------------------------------------------
#define QSTR 72
#define ATILE (128 * QSTR * 2)
#define KV_OFF ATILE
#define KVSTAGE (2 * ATILE)
#define ATTN_SMEM (ATILE + 2 * KVSTAGE)

__global__ __launch_bounds__(256, 1) void attn_kernel()
{
    extern __shared__ char smem[];
    const uint32_t sb = smem_to_u32(smem);
    const int tid = threadIdx.x;
    const int wid = tid >> 5, lane = tid & 31;
    const int gid = lane >> 2, tig = lane & 3;
    const int q0 = blockIdx.x * 128;
    const int bh = blockIdx.y;
    const int b = bh >> 4, h = bh & 15;

    const __nv_bfloat16* Qg = g_Qh + (size_t)(b * SS + q0) * HD + h * DD;
    const __nv_bfloat16* Kg = g_Kh + (size_t)(b * SS) * HD + h * DD;
    const __nv_bfloat16* Vg = g_Vh + (size_t)(b * SS) * HD + h * DD;

#pragma unroll
    for (int p = 0; p < 4; p++) {
        int idx = tid + p * 256;
        int row = idx >> 3, seg = idx & 7;
        cp16(sb + (uint32_t)(row * QSTR + seg * 8) * 2,
             Qg + (size_t)row * HD + seg * 8);
    }
    cp_commit();

#define LOAD_KV(st, it) do { \
    int kvb = (it) * 128; \
    _Pragma("unroll") \
    for (int p = 0; p < 8; p++) { \
        int idx = tid + p * 256; \
        int tile = idx >> 10, row = (idx >> 3) & 127, seg = idx & 7; \
        const __nv_bfloat16* src = tile ? Vg : Kg; \
        uint32_t dst = sb + KV_OFF + (st) * KVSTAGE + tile * ATILE \
                       + (uint32_t)(row * QSTR + seg * 8) * 2; \
        cp16(dst, src + (size_t)(kvb + row) * HD + seg * 8); \
    } \
    cp_commit(); \
} while (0)

    LOAD_KV(0, 0);
    cp_wait<1>();
    __syncthreads();

    uint32_t qf[4][4];
#pragma unroll
    for (int kk = 0; kk < 4; kk++) {
        int mrow = wid * 16 + ((lane >> 3) & 1) * 8 + (lane & 7);
        int mcol = kk * 16 + (lane >> 4) * 8;
        ldm_x4(qf[kk], sb + (uint32_t)(mrow * QSTR + mcol) * 2);
    }

    float o[8][4];
#pragma unroll
    for (int nt = 0; nt < 8; nt++)
#pragma unroll
        for (int e = 0; e < 4; e++) o[nt][e] = 0.0f;
    float m0 = -1e30f, m1 = -1e30f, l0 = 0.0f, l1 = 0.0f;

    for (int it = 0; it < 16; it++) {
        if (it < 15) { LOAD_KV((it + 1) & 1, it + 1); cp_wait<1>(); }
        else         { cp_wait<0>(); }
        __syncthreads();

        const uint32_t Kb = sb + KV_OFF + (it & 1) * KVSTAGE;
        const uint32_t Vb = Kb + ATILE;

        float s[16][4];
#pragma unroll
        for (int nt = 0; nt < 16; nt++)
#pragma unroll
            for (int e = 0; e < 4; e++) s[nt][e] = 0.0f;

#pragma unroll
        for (int kk = 0; kk < 4; kk++) {
#pragma unroll
            for (int np = 0; np < 8; np++) {
                int nrow = np * 16 + (lane >> 4) * 8 + (lane & 7);
                int ncol = kk * 16 + ((lane >> 3) & 1) * 8;
                uint32_t r[4];
                ldm_x4(r, Kb + (uint32_t)(nrow * QSTR + ncol) * 2);
                mma_bf16(s[np * 2],     qf[kk], r);
                mma_bf16(s[np * 2 + 1], qf[kk], r + 2);
            }
        }

        float mx0 = s[0][0], mx1 = s[0][2];
#pragma unroll
        for (int nt = 0; nt < 16; nt++) {
            mx0 = fmaxf(mx0, fmaxf(s[nt][0], s[nt][1]));
            mx1 = fmaxf(mx1, fmaxf(s[nt][2], s[nt][3]));
        }
        mx0 = fmaxf(mx0, __shfl_xor_sync(0xffffffffu, mx0, 1));
        mx0 = fmaxf(mx0, __shfl_xor_sync(0xffffffffu, mx0, 2));
        mx1 = fmaxf(mx1, __shfl_xor_sync(0xffffffffu, mx1, 1));
        mx1 = fmaxf(mx1, __shfl_xor_sync(0xffffffffu, mx1, 2));
        float mn0 = fmaxf(m0, mx0), mn1 = fmaxf(m1, mx1);
        float al0 = exp2_poly(m0 - mn0), al1 = exp2_poly(m1 - mn1);
        m0 = mn0; m1 = mn1;

        float rs0 = 0.0f, rs1 = 0.0f;
#pragma unroll
        for (int nt = 0; nt < 16; nt++) {
            s[nt][0] = exp2_poly(s[nt][0] - mn0); rs0 += s[nt][0];
            s[nt][1] = exp2_poly(s[nt][1] - mn0); rs0 += s[nt][1];
            s[nt][2] = exp2_poly(s[nt][2] - mn1); rs1 += s[nt][2];
            s[nt][3] = exp2_poly(s[nt][3] - mn1); rs1 += s[nt][3];
        }
        rs0 += __shfl_xor_sync(0xffffffffu, rs0, 1);
        rs0 += __shfl_xor_sync(0xffffffffu, rs0, 2);
        rs1 += __shfl_xor_sync(0xffffffffu, rs1, 1);
        rs1 += __shfl_xor_sync(0xffffffffu, rs1, 2);
        l0 = l0 * al0 + rs0;
        l1 = l1 * al1 + rs1;
#pragma unroll
        for (int nt = 0; nt < 8; nt++) {
            o[nt][0] *= al0; o[nt][1] *= al0;
            o[nt][2] *= al1; o[nt][3] *= al1;
        }

#pragma unroll
        for (int t = 0; t < 8; t++) {
            uint32_t pa[4];
            asm("cvt.rn.bf16x2.f32 %0, %1, %2;" : "=r"(pa[0])
                : "f"(s[2 * t][1]), "f"(s[2 * t][0]));
            asm("cvt.rn.bf16x2.f32 %0, %1, %2;" : "=r"(pa[1])
                : "f"(s[2 * t][3]), "f"(s[2 * t][2]));
            asm("cvt.rn.bf16x2.f32 %0, %1, %2;" : "=r"(pa[2])
                : "f"(s[2 * t + 1][1]), "f"(s[2 * t + 1][0]));
            asm("cvt.rn.bf16x2.f32 %0, %1, %2;" : "=r"(pa[3])
                : "f"(s[2 * t + 1][3]), "f"(s[2 * t + 1][2]));
#pragma unroll
            for (int nh = 0; nh < 4; nh++) {
                int kvrow = t * 16 + ((lane >> 3) & 1) * 8 + (lane & 7);
                int col   = nh * 16 + (lane >> 4) * 8;
                uint32_t r[4];
                ldm_x4_t(r, Vb + (uint32_t)(kvrow * QSTR + col) * 2);
                mma_bf16(o[nh * 2],     pa, r);
                mma_bf16(o[nh * 2 + 1], pa, r + 2);
            }
        }
        __syncthreads();
    }

    const float rl0 = 1.0f / l0, rl1 = 1.0f / l1;
    const size_t row0 = (size_t)(b * SS + q0 + wid * 16 + gid) * HD;
    const size_t row1 = row0 + 8 * HD;
#pragma unroll
    for (int nt = 0; nt < 8; nt++) {
        int col = h * DD + nt * 8 + 2 * tig;
        *(__nv_bfloat162*)(g_AttnH + row0 + col) =
            __halves2bfloat162(__float2bfloat16(o[nt][0] * rl0),
                               __float2bfloat16(o[nt][1] * rl0));
        *(__nv_bfloat162*)(g_AttnH + row1 + col) =
            __halves2bfloat162(__float2bfloat16(o[nt][2] * rl1),
                               __float2bfloat16(o[nt][3] * rl1));
    }
}

// ---------------------------------------------------------------------------
extern "C" void kernel_launch(void* const* d_in, const int* in_sizes, int n_in,
                              void* d_out, int out_size)
{
    const float* emb  = (const float*)d_in[0];
    const float* Wq   = (const float*)d_in[1];
    const float* Wk   = (const float*)d_in[2];
    const float* Wv   = (const float*)d_in[3];
    const float* Wu   = (const float*)d_in[4];
    const float* bu   = (const float*)d_in[5];
    const float* qn_w = (const float*)d_in[6];
    const float* qn_b = (const float*)d_in[7];
    const float* kn_w = (const float*)d_in[8];
    const float* kn_b = (const float*)d_in[9];
    float* out = (float*)d_out;

    (void)in_sizes; (void)n_in; (void)out_size;

    cudaFuncSetAttribute(attn_kernel,
                         cudaFuncAttributeMaxDynamicSharedMemorySize, ATTN_SMEM);
    cudaFuncSetAttribute(mma_gemm_kernel,
                         cudaFuncAttributeMaxDynamicSharedMemorySize, GEMM_SMEM);

    __nv_bfloat16 *EmbH_p, *AttnH_p, *Wh_p;
    float *Q_p, *K_p;
    cudaGetSymbolAddress((void**)&EmbH_p, g_EmbH);
    cudaGetSymbolAddress((void**)&AttnH_p, g_AttnH);
    cudaGetSymbolAddress((void**)&Wh_p, g_Wh);
    cudaGetSymbolAddress((void**)&Q_p, g_Q);
    cudaGetSymbolAddress((void**)&K_p, g_K);

    // 1) emb and weights -> bf16
    conv_kernel<<<(MTOT * EE / 8) / 256, 256>>>(emb, EmbH_p);
    conv_w_kernel<<<dim3((EE * HD / 8) / 256, 4), 256>>>(Wq, Wk, Wv, Wu);

    // 2) QKV projections (single-product bf16 mma.sync); V written bf16 directly
    mma_gemm_kernel<<<dim3(HD / 128, MTOT / 128, 3), 256, GEMM_SMEM>>>(
        EmbH_p, Wh_p, Q_p, K_p, nullptr, nullptr);

    // 3) LayerNorm -> bf16 Qh (with 0.125*log2e) / Kh
    ln_kernel<<<(2 * MTOT * HH) / 8, 256>>>(qn_w, qn_b, kn_w, kn_b);

    // 4) Attention (tensor cores + FMA-pipe exp) -> g_AttnH (bf16)
    attn_kernel<<<dim3(SS / 128, BB * HH), 256, ATTN_SMEM>>>();

    // 5) Output projection + bias + residual
    mma_gemm_kernel<<<dim3(EE / 128, MTOT / 128, 1), 256, GEMM_SMEM>>>(
        AttnH_p, Wh_p + (size_t)3 * EE * HD, out, nullptr, emb, bu);
}

// round 9
// speedup vs baseline: 5.8736x; 1.1124x over previous
#include <cuda_runtime.h>
#include <cuda_bf16.h>
#include <cstdint>

#define BB 2
#define SS 2048
#define EE 1024
#define HH 16
#define DD 64
#define MTOT (BB*SS)    // 4096
#define HD (HH*DD)      // 1024

// bf16 operands
__device__ __nv_bfloat16 g_Qh[(size_t)MTOT * HD];
__device__ __nv_bfloat16 g_Kh[(size_t)MTOT * HD];
__device__ __nv_bfloat16 g_Vh[(size_t)MTOT * HD];
__device__ __nv_bfloat16 g_EmbH[(size_t)MTOT * HD];   // emb bf16 (QKV A operand)
__device__ __nv_bfloat16 g_AttnH[(size_t)MTOT * HD];  // attn out bf16 (out-proj A)
// weights bf16: Wq @0, Wk @1M, Wv @2M, Wu @3M
__device__ __nv_bfloat16 g_Wh[(size_t)4 * EE * HD];

// ===========================================================================
// helpers (arch-portable: cp.async + ldmatrix + mma.sync, sm_80+ PTX)
// ===========================================================================
__device__ __forceinline__ uint32_t smem_to_u32(const void* p) {
    uint32_t a;
    asm("{ .reg .u64 t; cvta.to.shared.u64 t, %1; cvt.u32.u64 %0, t; }"
        : "=r"(a) : "l"(p));
    return a;
}
__device__ __forceinline__ void cp16(uint32_t d, const void* s) {
    asm volatile("cp.async.ca.shared.global [%0], [%1], 16;" :: "r"(d), "l"(s));
}
__device__ __forceinline__ void cp_commit() {
    asm volatile("cp.async.commit_group;" ::: "memory");
}
template <int N>
__device__ __forceinline__ void cp_wait() {
    asm volatile("cp.async.wait_group %0;" :: "n"(N) : "memory");
}
__device__ __forceinline__ void ldm_x4(uint32_t* r, uint32_t addr) {
    asm volatile("ldmatrix.sync.aligned.m8n8.x4.shared.b16 {%0,%1,%2,%3}, [%4];"
        : "=r"(r[0]), "=r"(r[1]), "=r"(r[2]), "=r"(r[3]) : "r"(addr));
}
__device__ __forceinline__ void ldm_x4_t(uint32_t* r, uint32_t addr) {
    asm volatile("ldmatrix.sync.aligned.m8n8.x4.trans.shared.b16 {%0,%1,%2,%3}, [%4];"
        : "=r"(r[0]), "=r"(r[1]), "=r"(r[2]), "=r"(r[3]) : "r"(addr));
}
__device__ __forceinline__ void mma_bf16(float* d, const uint32_t* a, const uint32_t* b) {
    asm volatile(
        "mma.sync.aligned.m16n8k16.row.col.f32.bf16.bf16.f32 "
        "{%0,%1,%2,%3}, {%4,%5,%6,%7}, {%8,%9}, {%0,%1,%2,%3};"
        : "+f"(d[0]), "+f"(d[1]), "+f"(d[2]), "+f"(d[3])
        : "r"(a[0]), "r"(a[1]), "r"(a[2]), "r"(a[3]), "r"(b[0]), "r"(b[1]));
}
// 2^y, degree-4 Taylor on [-0.5,0.5] (rel err ~6e-5). |y| <= ~16 guaranteed
// by LayerNorm'd Q/K (scores bounded, no max subtraction needed).
__device__ __forceinline__ float exp2_nomax(float y) {
    float t = y + 12582912.0f;                 // 1.5*2^23: round-to-nearest
    int ibits = __float_as_int(t) << 23;
    float f = y - (t - 12582912.0f);           // f in [-0.5, 0.5]
    float p = 9.6181e-3f;
    p = fmaf(p, f, 5.5504108664e-2f);
    p = fmaf(p, f, 2.4022650696e-1f);
    p = fmaf(p, f, 6.9314718056e-1f);
    p = fmaf(p, f, 1.0f);
    return __int_as_float(__float_as_int(p) + ibits);
}

// ===========================================================================
// fp32 -> bf16 conversion kernels
// ===========================================================================
__global__ __launch_bounds__(256) void conv_kernel(
    const float* __restrict__ src, __nv_bfloat16* __restrict__ dst)
{
    int i = blockIdx.x * blockDim.x + threadIdx.x;   // over n/8
    float4 a = ((const float4*)src)[2 * i + 0];
    float4 b = ((const float4*)src)[2 * i + 1];
    __nv_bfloat162* d = (__nv_bfloat162*)dst + 4 * i;
    d[0] = __halves2bfloat162(__float2bfloat16(a.x), __float2bfloat16(a.y));
    d[1] = __halves2bfloat162(__float2bfloat16(a.z), __float2bfloat16(a.w));
    d[2] = __halves2bfloat162(__float2bfloat16(b.x), __float2bfloat16(b.y));
    d[3] = __halves2bfloat162(__float2bfloat16(b.z), __float2bfloat16(b.w));
}

__global__ __launch_bounds__(256) void conv_w_kernel(
    const float* __restrict__ Wq, const float* __restrict__ Wk,
    const float* __restrict__ Wv, const float* __restrict__ Wu)
{
    int z = blockIdx.y;
    const float* src = (z == 0) ? Wq : (z == 1) ? Wk : (z == 2) ? Wv : Wu;
    size_t base = (size_t)z * EE * HD;
    int i = blockIdx.x * blockDim.x + threadIdx.x;   // over 1M/8
    float4 a = ((const float4*)src)[2 * i + 0];
    float4 b = ((const float4*)src)[2 * i + 1];
    __nv_bfloat162* d = (__nv_bfloat162*)(g_Wh + base) + 4 * i;
    d[0] = __halves2bfloat162(__float2bfloat16(a.x), __float2bfloat16(a.y));
    d[1] = __halves2bfloat162(__float2bfloat16(a.z), __float2bfloat16(a.w));
    d[2] = __halves2bfloat162(__float2bfloat16(b.x), __float2bfloat16(b.y));
    d[3] = __halves2bfloat162(__float2bfloat16(b.z), __float2bfloat16(b.w));
}

// ===========================================================================
// bf16 mma.sync GEMM: C[m,n] = sum_k A[m,k]*B[n,k]
// Block 128x128, BK=32, 8 warps (warp tile 32x64), cp.async double buffer.
// Epilogue modes: z==2 -> bf16 to g_Vh; emb!=null -> fp32 + bu + emb residual;
// else -> fused per-head LayerNorm -> bf16 to g_Qh (z=0, with 0.125*log2e) /
// g_Kh (z=1). Warp tile spans exactly one head (64 cols), so LN reduces over
// the 4-thread tig group via shfl_xor 1,2.
// ===========================================================================
#define ASTR 40
#define TILE_BYTES (128 * ASTR * 2)       // 10240
#define STAGE_BYTES (2 * TILE_BYTES)      // 20480
#define GEMM_SMEM (2 * STAGE_BYTES)       // 40960

__global__ __launch_bounds__(256, 1) void mma_gemm_kernel(
    const __nv_bfloat16* __restrict__ A,
    const __nv_bfloat16* __restrict__ Wall,
    float* Cout,
    const float* __restrict__ emb, const float* __restrict__ bu,
    const float* __restrict__ qn_w, const float* __restrict__ qn_b,
    const float* __restrict__ kn_w, const float* __restrict__ kn_b)
{
    extern __shared__ char smem[];
    const uint32_t sb = smem_to_u32(smem);
    const int tid = threadIdx.x;
    const int wid = tid >> 5, lane = tid & 31;
    const int bn = blockIdx.x * 128;
    const int bm = blockIdx.y * 128;
    const int z = blockIdx.z;

    const __nv_bfloat16* Bp = Wall + (size_t)z * EE * HD;
    const int wm = wid & 3;
    const int wn = wid >> 2;

    float acc[2][8][4];
#pragma unroll
    for (int mt = 0; mt < 2; mt++)
#pragma unroll
        for (int nt = 0; nt < 8; nt++)
#pragma unroll
            for (int e = 0; e < 4; e++) acc[mt][nt][e] = 0.0f;

#define LOAD_STAGE(st, kt) do { \
    _Pragma("unroll") \
    for (int it = 0; it < 4; it++) { \
        int idx = tid + it * 256; \
        int tile = idx >> 9, rem = idx & 511, row = rem >> 2, seg = rem & 3; \
        const __nv_bfloat16* srcp = tile ? Bp : A; \
        int grow = (tile ? bn : bm) + row; \
        uint32_t dst = sb + (st) * STAGE_BYTES + tile * TILE_BYTES \
                       + (uint32_t)(row * ASTR + seg * 8) * 2; \
        cp16(dst, srcp + (size_t)grow * 1024 + (kt) + seg * 8); \
    } \
    cp_commit(); \
} while (0)

    LOAD_STAGE(0, 0);

    for (int ch = 0; ch < 32; ch++) {
        if (ch < 31) { LOAD_STAGE((ch + 1) & 1, (ch + 1) * 32); cp_wait<1>(); }
        else         { cp_wait<0>(); }
        __syncthreads();

        const uint32_t aA = sb + (ch & 1) * STAGE_BYTES;
        const uint32_t aB = aA + TILE_BYTES;

#pragma unroll
        for (int kk = 0; kk < 2; kk++) {
            const int k0 = kk * 16;
            uint32_t ah[2][4], bh[8][2];
#pragma unroll
            for (int mt = 0; mt < 2; mt++) {
                int mrow = wm * 32 + mt * 16 + ((lane >> 3) & 1) * 8 + (lane & 7);
                int mcol = k0 + (lane >> 4) * 8;
                ldm_x4(ah[mt], aA + (uint32_t)(mrow * ASTR + mcol) * 2);
            }
#pragma unroll
            for (int np = 0; np < 4; np++) {
                int nrow = wn * 64 + np * 16 + (lane >> 4) * 8 + (lane & 7);
                int ncol = k0 + ((lane >> 3) & 1) * 8;
                uint32_t r[4];
                ldm_x4(r, aB + (uint32_t)(nrow * ASTR + ncol) * 2);
                bh[np * 2][0] = r[0]; bh[np * 2][1] = r[1];
                bh[np * 2 + 1][0] = r[2]; bh[np * 2 + 1][1] = r[3];
            }
#pragma unroll
            for (int mt = 0; mt < 2; mt++)
#pragma unroll
                for (int nt = 0; nt < 8; nt++) mma_bf16(acc[mt][nt], ah[mt], bh[nt]);
        }
        __syncthreads();
    }

    const int tig = lane & 3, gid = lane >> 2;
    if (z == 2) {
        // V: write bf16 directly
#pragma unroll
        for (int mt = 0; mt < 2; mt++) {
            int r0 = bm + wm * 32 + mt * 16 + gid;
#pragma unroll
            for (int nt = 0; nt < 8; nt++) {
                int n = bn + wn * 64 + nt * 8 + tig * 2;
                *(__nv_bfloat162*)(g_Vh + (size_t)r0 * HD + n) =
                    __halves2bfloat162(__float2bfloat16(acc[mt][nt][0]),
                                       __float2bfloat16(acc[mt][nt][1]));
                *(__nv_bfloat162*)(g_Vh + (size_t)(r0 + 8) * HD + n) =
                    __halves2bfloat162(__float2bfloat16(acc[mt][nt][2]),
                                       __float2bfloat16(acc[mt][nt][3]));
            }
        }
    } else if (emb) {
        // out-projection epilogue: + bu + emb residual, fp32 output
#pragma unroll
        for (int mt = 0; mt < 2; mt++) {
            int r0 = bm + wm * 32 + mt * 16 + gid;
#pragma unroll
            for (int nt = 0; nt < 8; nt++) {
                int n = bn + wn * 64 + nt * 8 + tig * 2;
                float2 v0 = make_float2(acc[mt][nt][0], acc[mt][nt][1]);
                float2 v1 = make_float2(acc[mt][nt][2], acc[mt][nt][3]);
                float b0 = bu[n], b1 = bu[n + 1];
                float2 e0 = *(const float2*)(emb + (size_t)r0 * EE + n);
                float2 e1 = *(const float2*)(emb + (size_t)(r0 + 8) * EE + n);
                v0.x += b0 + e0.x; v0.y += b1 + e0.y;
                v1.x += b0 + e1.x; v1.y += b1 + e1.y;
                *(float2*)(Cout + (size_t)r0 * 1024 + n) = v0;
                *(float2*)(Cout + (size_t)(r0 + 8) * 1024 + n) = v1;
            }
        }
    } else {
        // fused LayerNorm epilogue (Q: z==0 with folded 0.125*log2e; K: z==1)
        const float scale = (z == 0) ? 0.1803368801111243f : 1.0f;
        const float* lw = (z == 0) ? qn_w : kn_w;
        const float* lb = (z == 0) ? qn_b : kn_b;
        __nv_bfloat16* dstb = (z == 0) ? g_Qh : g_Kh;
        float wv[16], bv[16];
#pragma unroll
        for (int nt = 0; nt < 8; nt++) {
            int c = nt * 8 + tig * 2;   // column within head
            float2 wp = *(const float2*)(lw + c);
            float2 bp = *(const float2*)(lb + c);
            wv[nt * 2] = wp.x; wv[nt * 2 + 1] = wp.y;
            bv[nt * 2] = bp.x; bv[nt * 2 + 1] = bp.y;
        }
#pragma unroll
        for (int mt = 0; mt < 2; mt++) {
            int r0 = bm + wm * 32 + mt * 16 + gid;
#pragma unroll
            for (int half = 0; half < 2; half++) {
                float sum = 0.0f, sq = 0.0f;
#pragma unroll
                for (int nt = 0; nt < 8; nt++) {
                    float v0 = acc[mt][nt][half * 2];
                    float v1 = acc[mt][nt][half * 2 + 1];
                    sum += v0 + v1;
                    sq = fmaf(v0, v0, sq); sq = fmaf(v1, v1, sq);
                }
                sum += __shfl_xor_sync(0xffffffffu, sum, 1);
                sum += __shfl_xor_sync(0xffffffffu, sum, 2);
                sq  += __shfl_xor_sync(0xffffffffu, sq, 1);
                sq  += __shfl_xor_sync(0xffffffffu, sq, 2);
                float mean = sum * (1.0f / 64.0f);
                float var = sq * (1.0f / 64.0f) - mean * mean;
                float inv = rsqrtf(var + 1e-5f) * scale;
                int row = r0 + half * 8;
#pragma unroll
                for (int nt = 0; nt < 8; nt++) {
                    int n = bn + wn * 64 + nt * 8 + tig * 2;
                    float v0 = acc[mt][nt][half * 2];
                    float v1 = acc[mt][nt][half * 2 + 1];
                    float y0 = fmaf((v0 - mean) * inv, wv[nt * 2],     bv[nt * 2] * scale);
                    float y1 = fmaf((v1 - mean) * inv, wv[nt * 2 + 1], bv[nt * 2 + 1] * scale);
                    *(__nv_bfloat162*)(dstb + (size_t)row * HD + n) =
                        __halves2bfloat162(__float2bfloat16(y0), __float2bfloat16(y1));
                }
            }
        }
    }
}

// ---------------------------------------------------------------------------
// Flash attention on mma.sync (bf16). grid (S/128, B*H), 256 threads (8 warps).
// Warp = 16 q rows. KV tile 128. Scores in log2 units (scale folded into Q).
// MAX-FREE softmax: LN'd Q/K bound |score| <= ~16 log2-units, so exp2 cannot
// overflow fp32; P = exp2(s) raw, l accumulated per-thread, reduced once.
// Output bf16 into g_AttnH.
// ---------------------------------------------------------------------------
#define QSTR 72
#define ATILE (128 * QSTR * 2)
#define KV_OFF ATILE
#define KVSTAGE (2 * ATILE)
#define ATTN_SMEM (ATILE + 2 * KVSTAGE)

__global__ __launch_bounds__(256, 1) void attn_kernel()
{
    extern __shared__ char smem[];
    const uint32_t sb = smem_to_u32(smem);
    const int tid = threadIdx.x;
    const int wid = tid >> 5, lane = tid & 31;
    const int gid = lane >> 2, tig = lane & 3;
    const int q0 = blockIdx.x * 128;
    const int bh = blockIdx.y;
    const int b = bh >> 4, h = bh & 15;

    const __nv_bfloat16* Qg = g_Qh + (size_t)(b * SS + q0) * HD + h * DD;
    const __nv_bfloat16* Kg = g_Kh + (size_t)(b * SS) * HD + h * DD;
    const __nv_bfloat16* Vg = g_Vh + (size_t)(b * SS) * HD + h * DD;

#pragma unroll
    for (int p = 0; p < 4; p++) {
        int idx = tid + p * 256;
        int row = idx >> 3, seg = idx & 7;
        cp16(sb + (uint32_t)(row * QSTR + seg * 8) * 2,
             Qg + (size_t)row * HD + seg * 8);
    }
    cp_commit();

#define LOAD_KV(st, it) do { \
    int kvb = (it) * 128; \
    _Pragma("unroll") \
    for (int p = 0; p < 8; p++) { \
        int idx = tid + p * 256; \
        int tile = idx >> 10, row = (idx >> 3) & 127, seg = idx & 7; \
        const __nv_bfloat16* src = tile ? Vg : Kg; \
        uint32_t dst = sb + KV_OFF + (st) * KVSTAGE + tile * ATILE \
                       + (uint32_t)(row * QSTR + seg * 8) * 2; \
        cp16(dst, src + (size_t)(kvb + row) * HD + seg * 8); \
    } \
    cp_commit(); \
} while (0)

    LOAD_KV(0, 0);
    cp_wait<1>();
    __syncthreads();

    uint32_t qf[4][4];
#pragma unroll
    for (int kk = 0; kk < 4; kk++) {
        int mrow = wid * 16 + ((lane >> 3) & 1) * 8 + (lane & 7);
        int mcol = kk * 16 + (lane >> 4) * 8;
        ldm_x4(qf[kk], sb + (uint32_t)(mrow * QSTR + mcol) * 2);
    }

    float o[8][4];
#pragma unroll
    for (int nt = 0; nt < 8; nt++)
#pragma unroll
        for (int e = 0; e < 4; e++) o[nt][e] = 0.0f;
    float l0 = 0.0f, l1 = 0.0f;

    for (int it = 0; it < 16; it++) {
        if (it < 15) { LOAD_KV((it + 1) & 1, it + 1); cp_wait<1>(); }
        else         { cp_wait<0>(); }
        __syncthreads();

        const uint32_t Kb = sb + KV_OFF + (it & 1) * KVSTAGE;
        const uint32_t Vb = Kb + ATILE;

        float s[16][4];
#pragma unroll
        for (int nt = 0; nt < 16; nt++)
#pragma unroll
            for (int e = 0; e < 4; e++) s[nt][e] = 0.0f;

#pragma unroll
        for (int kk = 0; kk < 4; kk++) {
#pragma unroll
            for (int np = 0; np < 8; np++) {
                int nrow = np * 16 + (lane >> 4) * 8 + (lane & 7);
                int ncol = kk * 16 + ((lane >> 3) & 1) * 8;
                uint32_t r[4];
                ldm_x4(r, Kb + (uint32_t)(nrow * QSTR + ncol) * 2);
                mma_bf16(s[np * 2],     qf[kk], r);
                mma_bf16(s[np * 2 + 1], qf[kk], r + 2);
            }
        }

        // max-free exp2 + per-thread l partials
#pragma unroll
        for (int nt = 0; nt < 16; nt++) {
            s[nt][0] = exp2_nomax(s[nt][0]); l0 += s[nt][0];
            s[nt][1] = exp2_nomax(s[nt][1]); l0 += s[nt][1];
            s[nt][2] = exp2_nomax(s[nt][2]); l1 += s[nt][2];
            s[nt][3] = exp2_nomax(s[nt][3]); l1 += s[nt][3];
        }

        // O += P V   (P from registers; V b-frags via ldmatrix.trans)
#pragma unroll
        for (int t = 0; t < 8; t++) {
            uint32_t pa[4];
            asm("cvt.rn.bf16x2.f32 %0, %1, %2;" : "=r"(pa[0])
                : "f"(s[2 * t][1]), "f"(s[2 * t][0]));
            asm("cvt.rn.bf16x2.f32 %0, %1, %2;" : "=r"(pa[1])
                : "f"(s[2 * t][3]), "f"(s[2 * t][2]));
            asm("cvt.rn.bf16x2.f32 %0, %1, %2;" : "=r"(pa[2])
                : "f"(s[2 * t + 1][1]), "f"(s[2 * t + 1][0]));
            asm("cvt.rn.bf16x2.f32 %0, %1, %2;" : "=r"(pa[3])
                : "f"(s[2 * t + 1][3]), "f"(s[2 * t + 1][2]));
#pragma unroll
            for (int nh = 0; nh < 4; nh++) {
                int kvrow = t * 16 + ((lane >> 3) & 1) * 8 + (lane & 7);
                int col   = nh * 16 + (lane >> 4) * 8;
                uint32_t r[4];
                ldm_x4_t(r, Vb + (uint32_t)(kvrow * QSTR + col) * 2);
                mma_bf16(o[nh * 2],     pa, r);
                mma_bf16(o[nh * 2 + 1], pa, r + 2);
            }
        }
        __syncthreads();
    }

    // reduce l over the tig group once
    l0 += __shfl_xor_sync(0xffffffffu, l0, 1);
    l0 += __shfl_xor_sync(0xffffffffu, l0, 2);
    l1 += __shfl_xor_sync(0xffffffffu, l1, 1);
    l1 += __shfl_xor_sync(0xffffffffu, l1, 2);

    const float rl0 = 1.0f / l0, rl1 = 1.0f / l1;
    const size_t row0 = (size_t)(b * SS + q0 + wid * 16 + gid) * HD;
    const size_t row1 = row0 + 8 * HD;
#pragma unroll
    for (int nt = 0; nt < 8; nt++) {
        int col = h * DD + nt * 8 + 2 * tig;
        *(__nv_bfloat162*)(g_AttnH + row0 + col) =
            __halves2bfloat162(__float2bfloat16(o[nt][0] * rl0),
                               __float2bfloat16(o[nt][1] * rl0));
        *(__nv_bfloat162*)(g_AttnH + row1 + col) =
            __halves2bfloat162(__float2bfloat16(o[nt][2] * rl1),
                               __float2bfloat16(o[nt][3] * rl1));
    }
}

// ---------------------------------------------------------------------------
extern "C" void kernel_launch(void* const* d_in, const int* in_sizes, int n_in,
                              void* d_out, int out_size)
{
    const float* emb  = (const float*)d_in[0];
    const float* Wq   = (const float*)d_in[1];
    const float* Wk   = (const float*)d_in[2];
    const float* Wv   = (const float*)d_in[3];
    const float* Wu   = (const float*)d_in[4];
    const float* bu   = (const float*)d_in[5];
    const float* qn_w = (const float*)d_in[6];
    const float* qn_b = (const float*)d_in[7];
    const float* kn_w = (const float*)d_in[8];
    const float* kn_b = (const float*)d_in[9];
    float* out = (float*)d_out;

    (void)in_sizes; (void)n_in; (void)out_size;

    cudaFuncSetAttribute(attn_kernel,
                         cudaFuncAttributeMaxDynamicSharedMemorySize, ATTN_SMEM);
    cudaFuncSetAttribute(mma_gemm_kernel,
                         cudaFuncAttributeMaxDynamicSharedMemorySize, GEMM_SMEM);

    __nv_bfloat16 *EmbH_p, *AttnH_p, *Wh_p;
    cudaGetSymbolAddress((void**)&EmbH_p, g_EmbH);
    cudaGetSymbolAddress((void**)&AttnH_p, g_AttnH);
    cudaGetSymbolAddress((void**)&Wh_p, g_Wh);

    // 1) emb and weights -> bf16
    conv_kernel<<<(MTOT * EE / 8) / 256, 256>>>(emb, EmbH_p);
    conv_w_kernel<<<dim3((EE * HD / 8) / 256, 4), 256>>>(Wq, Wk, Wv, Wu);

    // 2) QKV projections with fused LayerNorm epilogue -> Qh/Kh/Vh (bf16)
    mma_gemm_kernel<<<dim3(HD / 128, MTOT / 128, 3), 256, GEMM_SMEM>>>(
        EmbH_p, Wh_p, nullptr, nullptr, nullptr, qn_w, qn_b, kn_w, kn_b);

    // 3) Attention (tensor cores + max-free FMA-pipe exp2) -> g_AttnH (bf16)
    attn_kernel<<<dim3(SS / 128, BB * HH), 256, ATTN_SMEM>>>();

    // 4) Output projection + bias + residual
    mma_gemm_kernel<<<dim3(EE / 128, MTOT / 128, 1), 256, GEMM_SMEM>>>(
        AttnH_p, Wh_p + (size_t)3 * EE * HD, out, emb, bu,
        nullptr, nullptr, nullptr, nullptr);
}

// round 10
// speedup vs baseline: 5.9345x; 1.0104x over previous
#include <cuda_runtime.h>
#include <cuda_bf16.h>
#include <cstdint>

#define BB 2
#define SS 2048
#define EE 1024
#define HH 16
#define DD 64
#define MTOT (BB*SS)    // 4096
#define HD (HH*DD)      // 1024

// bf16 operands
__device__ __nv_bfloat16 g_Qh[(size_t)MTOT * HD];
__device__ __nv_bfloat16 g_Kh[(size_t)MTOT * HD];
__device__ __nv_bfloat16 g_Vh[(size_t)MTOT * HD];
__device__ __nv_bfloat16 g_EmbH[(size_t)MTOT * HD];   // emb bf16 (QKV A operand)
__device__ __nv_bfloat16 g_AttnH[(size_t)MTOT * HD];  // attn out bf16 (out-proj A)
// weights bf16: Wq @0, Wk @1M, Wv @2M, Wu @3M
__device__ __nv_bfloat16 g_Wh[(size_t)4 * EE * HD];

// ===========================================================================
// helpers (arch-portable: cp.async + ldmatrix + mma.sync, sm_80+ PTX)
// ===========================================================================
__device__ __forceinline__ uint32_t smem_to_u32(const void* p) {
    uint32_t a;
    asm("{ .reg .u64 t; cvta.to.shared.u64 t, %1; cvt.u32.u64 %0, t; }"
        : "=r"(a) : "l"(p));
    return a;
}
__device__ __forceinline__ void cp16(uint32_t d, const void* s) {
    asm volatile("cp.async.ca.shared.global [%0], [%1], 16;" :: "r"(d), "l"(s));
}
__device__ __forceinline__ void cp_commit() {
    asm volatile("cp.async.commit_group;" ::: "memory");
}
template <int N>
__device__ __forceinline__ void cp_wait() {
    asm volatile("cp.async.wait_group %0;" :: "n"(N) : "memory");
}
__device__ __forceinline__ void ldm_x4(uint32_t* r, uint32_t addr) {
    asm volatile("ldmatrix.sync.aligned.m8n8.x4.shared.b16 {%0,%1,%2,%3}, [%4];"
        : "=r"(r[0]), "=r"(r[1]), "=r"(r[2]), "=r"(r[3]) : "r"(addr));
}
__device__ __forceinline__ void ldm_x4_t(uint32_t* r, uint32_t addr) {
    asm volatile("ldmatrix.sync.aligned.m8n8.x4.trans.shared.b16 {%0,%1,%2,%3}, [%4];"
        : "=r"(r[0]), "=r"(r[1]), "=r"(r[2]), "=r"(r[3]) : "r"(addr));
}
__device__ __forceinline__ void mma_bf16(float* d, const uint32_t* a, const uint32_t* b) {
    asm volatile(
        "mma.sync.aligned.m16n8k16.row.col.f32.bf16.bf16.f32 "
        "{%0,%1,%2,%3}, {%4,%5,%6,%7}, {%8,%9}, {%0,%1,%2,%3};"
        : "+f"(d[0]), "+f"(d[1]), "+f"(d[2]), "+f"(d[3])
        : "r"(a[0]), "r"(a[1]), "r"(a[2]), "r"(a[3]), "r"(b[0]), "r"(b[1]));
}
// 2^y, degree-4 Taylor on [-0.5,0.5] (rel err ~6e-5). |y| <= ~16 guaranteed
// by LayerNorm'd Q/K (scores bounded, no max subtraction needed).
__device__ __forceinline__ float exp2_nomax(float y) {
    float t = y + 12582912.0f;                 // 1.5*2^23: round-to-nearest
    int ibits = __float_as_int(t) << 23;
    float f = y - (t - 12582912.0f);           // f in [-0.5, 0.5]
    float p = 9.6181e-3f;
    p = fmaf(p, f, 5.5504108664e-2f);
    p = fmaf(p, f, 2.4022650696e-1f);
    p = fmaf(p, f, 6.9314718056e-1f);
    p = fmaf(p, f, 1.0f);
    return __int_as_float(__float_as_int(p) + ibits);
}

// ===========================================================================
// fp32 -> bf16 conversion kernels
// ===========================================================================
__global__ __launch_bounds__(256) void conv_kernel(
    const float* __restrict__ src, __nv_bfloat16* __restrict__ dst)
{
    int i = blockIdx.x * blockDim.x + threadIdx.x;   // over n/8
    float4 a = ((const float4*)src)[2 * i + 0];
    float4 b = ((const float4*)src)[2 * i + 1];
    __nv_bfloat162* d = (__nv_bfloat162*)dst + 4 * i;
    d[0] = __halves2bfloat162(__float2bfloat16(a.x), __float2bfloat16(a.y));
    d[1] = __halves2bfloat162(__float2bfloat16(a.z), __float2bfloat16(a.w));
    d[2] = __halves2bfloat162(__float2bfloat16(b.x), __float2bfloat16(b.y));
    d[3] = __halves2bfloat162(__float2bfloat16(b.z), __float2bfloat16(b.w));
}

__global__ __launch_bounds__(256) void conv_w_kernel(
    const float* __restrict__ Wq, const float* __restrict__ Wk,
    const float* __restrict__ Wv, const float* __restrict__ Wu)
{
    int z = blockIdx.y;
    const float* src = (z == 0) ? Wq : (z == 1) ? Wk : (z == 2) ? Wv : Wu;
    size_t base = (size_t)z * EE * HD;
    int i = blockIdx.x * blockDim.x + threadIdx.x;   // over 1M/8
    float4 a = ((const float4*)src)[2 * i + 0];
    float4 b = ((const float4*)src)[2 * i + 1];
    __nv_bfloat162* d = (__nv_bfloat162*)(g_Wh + base) + 4 * i;
    d[0] = __halves2bfloat162(__float2bfloat16(a.x), __float2bfloat16(a.y));
    d[1] = __halves2bfloat162(__float2bfloat16(a.z), __float2bfloat16(a.w));
    d[2] = __halves2bfloat162(__float2bfloat16(b.x), __float2bfloat16(b.y));
    d[3] = __halves2bfloat162(__float2bfloat16(b.z), __float2bfloat16(b.w));
}

// ===========================================================================
// bf16 mma.sync GEMM: C[m,n] = sum_k A[m,k]*B[n,k]
// Block 128x128, BK=32, 8 warps (warp tile 32x64), cp.async double buffer.
// Epilogue modes: z==2 -> bf16 to g_Vh; emb!=null -> fp32 + bu + emb residual;
// else -> fused per-head LayerNorm -> bf16 to g_Qh (z=0, with 0.125*log2e) /
// g_Kh (z=1).
// ===========================================================================
#define ASTR 40
#define TILE_BYTES (128 * ASTR * 2)       // 10240
#define STAGE_BYTES (2 * TILE_BYTES)      // 20480
#define GEMM_SMEM (2 * STAGE_BYTES)       // 40960

__global__ __launch_bounds__(256, 1) void mma_gemm_kernel(
    const __nv_bfloat16* __restrict__ A,
    const __nv_bfloat16* __restrict__ Wall,
    float* Cout,
    const float* __restrict__ emb, const float* __restrict__ bu,
    const float* __restrict__ qn_w, const float* __restrict__ qn_b,
    const float* __restrict__ kn_w, const float* __restrict__ kn_b)
{
    extern __shared__ char smem[];
    const uint32_t sb = smem_to_u32(smem);
    const int tid = threadIdx.x;
    const int wid = tid >> 5, lane = tid & 31;
    const int bn = blockIdx.x * 128;
    const int bm = blockIdx.y * 128;
    const int z = blockIdx.z;

    const __nv_bfloat16* Bp = Wall + (size_t)z * EE * HD;
    const int wm = wid & 3;
    const int wn = wid >> 2;

    float acc[2][8][4];
#pragma unroll
    for (int mt = 0; mt < 2; mt++)
#pragma unroll
        for (int nt = 0; nt < 8; nt++)
#pragma unroll
            for (int e = 0; e < 4; e++) acc[mt][nt][e] = 0.0f;

#define LOAD_STAGE(st, kt) do { \
    _Pragma("unroll") \
    for (int it = 0; it < 4; it++) { \
        int idx = tid + it * 256; \
        int tile = idx >> 9, rem = idx & 511, row = rem >> 2, seg = rem & 3; \
        const __nv_bfloat16* srcp = tile ? Bp : A; \
        int grow = (tile ? bn : bm) + row; \
        uint32_t dst = sb + (st) * STAGE_BYTES + tile * TILE_BYTES \
                       + (uint32_t)(row * ASTR + seg * 8) * 2; \
        cp16(dst, srcp + (size_t)grow * 1024 + (kt) + seg * 8); \
    } \
    cp_commit(); \
} while (0)

    LOAD_STAGE(0, 0);

    for (int ch = 0; ch < 32; ch++) {
        if (ch < 31) { LOAD_STAGE((ch + 1) & 1, (ch + 1) * 32); cp_wait<1>(); }
        else         { cp_wait<0>(); }
        __syncthreads();

        const uint32_t aA = sb + (ch & 1) * STAGE_BYTES;
        const uint32_t aB = aA + TILE_BYTES;

#pragma unroll
        for (int kk = 0; kk < 2; kk++) {
            const int k0 = kk * 16;
            uint32_t ah[2][4], bh[8][2];
#pragma unroll
            for (int mt = 0; mt < 2; mt++) {
                int mrow = wm * 32 + mt * 16 + ((lane >> 3) & 1) * 8 + (lane & 7);
                int mcol = k0 + (lane >> 4) * 8;
                ldm_x4(ah[mt], aA + (uint32_t)(mrow * ASTR + mcol) * 2);
            }
#pragma unroll
            for (int np = 0; np < 4; np++) {
                int nrow = wn * 64 + np * 16 + (lane >> 4) * 8 + (lane & 7);
                int ncol = k0 + ((lane >> 3) & 1) * 8;
                uint32_t r[4];
                ldm_x4(r, aB + (uint32_t)(nrow * ASTR + ncol) * 2);
                bh[np * 2][0] = r[0]; bh[np * 2][1] = r[1];
                bh[np * 2 + 1][0] = r[2]; bh[np * 2 + 1][1] = r[3];
            }
#pragma unroll
            for (int mt = 0; mt < 2; mt++)
#pragma unroll
                for (int nt = 0; nt < 8; nt++) mma_bf16(acc[mt][nt], ah[mt], bh[nt]);
        }
        __syncthreads();
    }

    const int tig = lane & 3, gid = lane >> 2;
    if (z == 2) {
        // V: write bf16 directly
#pragma unroll
        for (int mt = 0; mt < 2; mt++) {
            int r0 = bm + wm * 32 + mt * 16 + gid;
#pragma unroll
            for (int nt = 0; nt < 8; nt++) {
                int n = bn + wn * 64 + nt * 8 + tig * 2;
                *(__nv_bfloat162*)(g_Vh + (size_t)r0 * HD + n) =
                    __halves2bfloat162(__float2bfloat16(acc[mt][nt][0]),
                                       __float2bfloat16(acc[mt][nt][1]));
                *(__nv_bfloat162*)(g_Vh + (size_t)(r0 + 8) * HD + n) =
                    __halves2bfloat162(__float2bfloat16(acc[mt][nt][2]),
                                       __float2bfloat16(acc[mt][nt][3]));
            }
        }
    } else if (emb) {
        // out-projection epilogue: + bu + emb residual, fp32 output
#pragma unroll
        for (int mt = 0; mt < 2; mt++) {
            int r0 = bm + wm * 32 + mt * 16 + gid;
#pragma unroll
            for (int nt = 0; nt < 8; nt++) {
                int n = bn + wn * 64 + nt * 8 + tig * 2;
                float2 v0 = make_float2(acc[mt][nt][0], acc[mt][nt][1]);
                float2 v1 = make_float2(acc[mt][nt][2], acc[mt][nt][3]);
                float b0 = bu[n], b1 = bu[n + 1];
                float2 e0 = *(const float2*)(emb + (size_t)r0 * EE + n);
                float2 e1 = *(const float2*)(emb + (size_t)(r0 + 8) * EE + n);
                v0.x += b0 + e0.x; v0.y += b1 + e0.y;
                v1.x += b0 + e1.x; v1.y += b1 + e1.y;
                *(float2*)(Cout + (size_t)r0 * 1024 + n) = v0;
                *(float2*)(Cout + (size_t)(r0 + 8) * 1024 + n) = v1;
            }
        }
    } else {
        // fused LayerNorm epilogue (Q: z==0 with folded 0.125*log2e; K: z==1)
        const float scale = (z == 0) ? 0.1803368801111243f : 1.0f;
        const float* lw = (z == 0) ? qn_w : kn_w;
        const float* lb = (z == 0) ? qn_b : kn_b;
        __nv_bfloat16* dstb = (z == 0) ? g_Qh : g_Kh;
        float wv[16], bv[16];
#pragma unroll
        for (int nt = 0; nt < 8; nt++) {
            int c = nt * 8 + tig * 2;   // column within head
            float2 wp = *(const float2*)(lw + c);
            float2 bp = *(const float2*)(lb + c);
            wv[nt * 2] = wp.x; wv[nt * 2 + 1] = wp.y;
            bv[nt * 2] = bp.x; bv[nt * 2 + 1] = bp.y;
        }
#pragma unroll
        for (int mt = 0; mt < 2; mt++) {
            int r0 = bm + wm * 32 + mt * 16 + gid;
#pragma unroll
            for (int half = 0; half < 2; half++) {
                float sum = 0.0f, sq = 0.0f;
#pragma unroll
                for (int nt = 0; nt < 8; nt++) {
                    float v0 = acc[mt][nt][half * 2];
                    float v1 = acc[mt][nt][half * 2 + 1];
                    sum += v0 + v1;
                    sq = fmaf(v0, v0, sq); sq = fmaf(v1, v1, sq);
                }
                sum += __shfl_xor_sync(0xffffffffu, sum, 1);
                sum += __shfl_xor_sync(0xffffffffu, sum, 2);
                sq  += __shfl_xor_sync(0xffffffffu, sq, 1);
                sq  += __shfl_xor_sync(0xffffffffu, sq, 2);
                float mean = sum * (1.0f / 64.0f);
                float var = sq * (1.0f / 64.0f) - mean * mean;
                float inv = rsqrtf(var + 1e-5f) * scale;
                int row = r0 + half * 8;
#pragma unroll
                for (int nt = 0; nt < 8; nt++) {
                    int n = bn + wn * 64 + nt * 8 + tig * 2;
                    float v0 = acc[mt][nt][half * 2];
                    float v1 = acc[mt][nt][half * 2 + 1];
                    float y0 = fmaf((v0 - mean) * inv, wv[nt * 2],     bv[nt * 2] * scale);
                    float y1 = fmaf((v1 - mean) * inv, wv[nt * 2 + 1], bv[nt * 2 + 1] * scale);
                    *(__nv_bfloat162*)(dstb + (size_t)row * HD + n) =
                        __halves2bfloat162(__float2bfloat16(y0), __float2bfloat16(y1));
                }
            }
        }
    }
}

// ---------------------------------------------------------------------------
// Flash attention on mma.sync (bf16). grid (S/128, B*H), 256 threads (8 warps).
// Warp = 16 q rows. KV tile 128, processed in 16-col chunks: QK-mma -> exp2
// -> bf16 P -> PV-mma per chunk (live score state = 8 regs, not 64).
// __launch_bounds__(256,2): <=128 regs -> 2 CTAs/SM (4 warps/SMSP).
// Max-free softmax (LN-bounded scores). Output bf16 into g_AttnH.
// ---------------------------------------------------------------------------
#define QSTR 72
#define ATILE (128 * QSTR * 2)
#define KV_OFF ATILE
#define KVSTAGE (2 * ATILE)
#define ATTN_SMEM (ATILE + 2 * KVSTAGE)

__global__ __launch_bounds__(256, 2) void attn_kernel()
{
    extern __shared__ char smem[];
    const uint32_t sb = smem_to_u32(smem);
    const int tid = threadIdx.x;
    const int wid = tid >> 5, lane = tid & 31;
    const int gid = lane >> 2, tig = lane & 3;
    const int q0 = blockIdx.x * 128;
    const int bh = blockIdx.y;
    const int b = bh >> 4, h = bh & 15;

    const __nv_bfloat16* Qg = g_Qh + (size_t)(b * SS + q0) * HD + h * DD;
    const __nv_bfloat16* Kg = g_Kh + (size_t)(b * SS) * HD + h * DD;
    const __nv_bfloat16* Vg = g_Vh + (size_t)(b * SS) * HD + h * DD;

#pragma unroll
    for (int p = 0; p < 4; p++) {
        int idx = tid + p * 256;
        int row = idx >> 3, seg = idx & 7;
        cp16(sb + (uint32_t)(row * QSTR + seg * 8) * 2,
             Qg + (size_t)row * HD + seg * 8);
    }
    cp_commit();

#define LOAD_KV(st, it) do { \
    int kvb = (it) * 128; \
    _Pragma("unroll") \
    for (int p = 0; p < 8; p++) { \
        int idx = tid + p * 256; \
        int tile = idx >> 10, row = (idx >> 3) & 127, seg = idx & 7; \
        const __nv_bfloat16* src = tile ? Vg : Kg; \
        uint32_t dst = sb + KV_OFF + (st) * KVSTAGE + tile * ATILE \
                       + (uint32_t)(row * QSTR + seg * 8) * 2; \
        cp16(dst, src + (size_t)(kvb + row) * HD + seg * 8); \
    } \
    cp_commit(); \
} while (0)

    LOAD_KV(0, 0);
    cp_wait<1>();
    __syncthreads();

    uint32_t qf[4][4];
#pragma unroll
    for (int kk = 0; kk < 4; kk++) {
        int mrow = wid * 16 + ((lane >> 3) & 1) * 8 + (lane & 7);
        int mcol = kk * 16 + (lane >> 4) * 8;
        ldm_x4(qf[kk], sb + (uint32_t)(mrow * QSTR + mcol) * 2);
    }

    float o[8][4];
#pragma unroll
    for (int nt = 0; nt < 8; nt++)
#pragma unroll
        for (int e = 0; e < 4; e++) o[nt][e] = 0.0f;
    float l0 = 0.0f, l1 = 0.0f;

    for (int it = 0; it < 16; it++) {
        if (it < 15) { LOAD_KV((it + 1) & 1, it + 1); cp_wait<1>(); }
        else         { cp_wait<0>(); }
        __syncthreads();

        const uint32_t Kb = sb + KV_OFF + (it & 1) * KVSTAGE;
        const uint32_t Vb = Kb + ATILE;

        // per 16-kv-chunk: QK mma -> exp2 -> P bf16 -> PV mma
#pragma unroll
        for (int t = 0; t < 8; t++) {
            float s0[4] = {0.0f, 0.0f, 0.0f, 0.0f};
            float s1[4] = {0.0f, 0.0f, 0.0f, 0.0f};
            const int nrow = t * 16 + (lane >> 4) * 8 + (lane & 7);
#pragma unroll
            for (int kk = 0; kk < 4; kk++) {
                int ncol = kk * 16 + ((lane >> 3) & 1) * 8;
                uint32_t r[4];
                ldm_x4(r, Kb + (uint32_t)(nrow * QSTR + ncol) * 2);
                mma_bf16(s0, qf[kk], r);
                mma_bf16(s1, qf[kk], r + 2);
            }
            s0[0] = exp2_nomax(s0[0]); s0[1] = exp2_nomax(s0[1]);
            s0[2] = exp2_nomax(s0[2]); s0[3] = exp2_nomax(s0[3]);
            s1[0] = exp2_nomax(s1[0]); s1[1] = exp2_nomax(s1[1]);
            s1[2] = exp2_nomax(s1[2]); s1[3] = exp2_nomax(s1[3]);
            l0 += s0[0] + s0[1] + s1[0] + s1[1];
            l1 += s0[2] + s0[3] + s1[2] + s1[3];

            uint32_t pa[4];
            asm("cvt.rn.bf16x2.f32 %0, %1, %2;" : "=r"(pa[0]) : "f"(s0[1]), "f"(s0[0]));
            asm("cvt.rn.bf16x2.f32 %0, %1, %2;" : "=r"(pa[1]) : "f"(s0[3]), "f"(s0[2]));
            asm("cvt.rn.bf16x2.f32 %0, %1, %2;" : "=r"(pa[2]) : "f"(s1[1]), "f"(s1[0]));
            asm("cvt.rn.bf16x2.f32 %0, %1, %2;" : "=r"(pa[3]) : "f"(s1[3]), "f"(s1[2]));

            const int kvrow = t * 16 + ((lane >> 3) & 1) * 8 + (lane & 7);
#pragma unroll
            for (int nh = 0; nh < 4; nh++) {
                int col = nh * 16 + (lane >> 4) * 8;
                uint32_t r[4];
                ldm_x4_t(r, Vb + (uint32_t)(kvrow * QSTR + col) * 2);
                mma_bf16(o[nh * 2],     pa, r);
                mma_bf16(o[nh * 2 + 1], pa, r + 2);
            }
        }
        __syncthreads();
    }

    // reduce l over the tig group once
    l0 += __shfl_xor_sync(0xffffffffu, l0, 1);
    l0 += __shfl_xor_sync(0xffffffffu, l0, 2);
    l1 += __shfl_xor_sync(0xffffffffu, l1, 1);
    l1 += __shfl_xor_sync(0xffffffffu, l1, 2);

    const float rl0 = 1.0f / l0, rl1 = 1.0f / l1;
    const size_t row0 = (size_t)(b * SS + q0 + wid * 16 + gid) * HD;
    const size_t row1 = row0 + 8 * HD;
#pragma unroll
    for (int nt = 0; nt < 8; nt++) {
        int col = h * DD + nt * 8 + 2 * tig;
        *(__nv_bfloat162*)(g_AttnH + row0 + col) =
            __halves2bfloat162(__float2bfloat16(o[nt][0] * rl0),
                               __float2bfloat16(o[nt][1] * rl0));
        *(__nv_bfloat162*)(g_AttnH + row1 + col) =
            __halves2bfloat162(__float2bfloat16(o[nt][2] * rl1),
                               __float2bfloat16(o[nt][3] * rl1));
    }
}

// ---------------------------------------------------------------------------
extern "C" void kernel_launch(void* const* d_in, const int* in_sizes, int n_in,
                              void* d_out, int out_size)
{
    const float* emb  = (const float*)d_in[0];
    const float* Wq   = (const float*)d_in[1];
    const float* Wk   = (const float*)d_in[2];
    const float* Wv   = (const float*)d_in[3];
    const float* Wu   = (const float*)d_in[4];
    const float* bu   = (const float*)d_in[5];
    const float* qn_w = (const float*)d_in[6];
    const float* qn_b = (const float*)d_in[7];
    const float* kn_w = (const float*)d_in[8];
    const float* kn_b = (const float*)d_in[9];
    float* out = (float*)d_out;

    (void)in_sizes; (void)n_in; (void)out_size;

    cudaFuncSetAttribute(attn_kernel,
                         cudaFuncAttributeMaxDynamicSharedMemorySize, ATTN_SMEM);
    cudaFuncSetAttribute(mma_gemm_kernel,
                         cudaFuncAttributeMaxDynamicSharedMemorySize, GEMM_SMEM);

    __nv_bfloat16 *EmbH_p, *AttnH_p, *Wh_p;
    cudaGetSymbolAddress((void**)&EmbH_p, g_EmbH);
    cudaGetSymbolAddress((void**)&AttnH_p, g_AttnH);
    cudaGetSymbolAddress((void**)&Wh_p, g_Wh);

    // 1) emb and weights -> bf16
    conv_kernel<<<(MTOT * EE / 8) / 256, 256>>>(emb, EmbH_p);
    conv_w_kernel<<<dim3((EE * HD / 8) / 256, 4), 256>>>(Wq, Wk, Wv, Wu);

    // 2) QKV projections with fused LayerNorm epilogue -> Qh/Kh/Vh (bf16)
    mma_gemm_kernel<<<dim3(HD / 128, MTOT / 128, 3), 256, GEMM_SMEM>>>(
        EmbH_p, Wh_p, nullptr, nullptr, nullptr, qn_w, qn_b, kn_w, kn_b);

    // 3) Attention (tensor cores + max-free FMA-pipe exp2) -> g_AttnH (bf16)
    attn_kernel<<<dim3(SS / 128, BB * HH), 256, ATTN_SMEM>>>();

    // 4) Output projection + bias + residual
    mma_gemm_kernel<<<dim3(EE / 128, MTOT / 128, 1), 256, GEMM_SMEM>>>(
        AttnH_p, Wh_p + (size_t)3 * EE * HD, out, emb, bu,
        nullptr, nullptr, nullptr, nullptr);
}

// round 11
// speedup vs baseline: 6.9281x; 1.1674x over previous
#include <cuda_runtime.h>
#include <cuda_bf16.h>
#include <cstdint>

#define BB 2
#define SS 2048
#define EE 1024
#define HH 16
#define DD 64
#define MTOT (BB*SS)    // 4096
#define HD (HH*DD)      // 1024

// bf16 operands
__device__ __nv_bfloat16 g_Qh[(size_t)MTOT * HD];
__device__ __nv_bfloat16 g_Kh[(size_t)MTOT * HD];
__device__ __nv_bfloat16 g_Vh[(size_t)MTOT * HD];
__device__ __nv_bfloat16 g_EmbH[(size_t)MTOT * HD];   // emb bf16 (QKV A operand)
__device__ __nv_bfloat16 g_AttnH[(size_t)MTOT * HD];  // attn out bf16 (out-proj A)
// weights bf16: Wq @0, Wk @1M, Wv @2M, Wu @3M
__device__ __nv_bfloat16 g_Wh[(size_t)4 * EE * HD];

// ===========================================================================
// helpers (arch-portable: cp.async + ldmatrix + mma.sync, sm_80+ PTX)
// ===========================================================================
__device__ __forceinline__ uint32_t smem_to_u32(const void* p) {
    uint32_t a;
    asm("{ .reg .u64 t; cvta.to.shared.u64 t, %1; cvt.u32.u64 %0, t; }"
        : "=r"(a) : "l"(p));
    return a;
}
__device__ __forceinline__ void cp16(uint32_t d, const void* s) {
    asm volatile("cp.async.ca.shared.global [%0], [%1], 16;" :: "r"(d), "l"(s));
}
__device__ __forceinline__ void cp_commit() {
    asm volatile("cp.async.commit_group;" ::: "memory");
}
template <int N>
__device__ __forceinline__ void cp_wait() {
    asm volatile("cp.async.wait_group %0;" :: "n"(N) : "memory");
}
__device__ __forceinline__ void ldm_x4(uint32_t* r, uint32_t addr) {
    asm volatile("ldmatrix.sync.aligned.m8n8.x4.shared.b16 {%0,%1,%2,%3}, [%4];"
        : "=r"(r[0]), "=r"(r[1]), "=r"(r[2]), "=r"(r[3]) : "r"(addr));
}
__device__ __forceinline__ void ldm_x4_t(uint32_t* r, uint32_t addr) {
    asm volatile("ldmatrix.sync.aligned.m8n8.x4.trans.shared.b16 {%0,%1,%2,%3}, [%4];"
        : "=r"(r[0]), "=r"(r[1]), "=r"(r[2]), "=r"(r[3]) : "r"(addr));
}
__device__ __forceinline__ void mma_bf16(float* d, const uint32_t* a, const uint32_t* b) {
    asm volatile(
        "mma.sync.aligned.m16n8k16.row.col.f32.bf16.bf16.f32 "
        "{%0,%1,%2,%3}, {%4,%5,%6,%7}, {%8,%9}, {%0,%1,%2,%3};"
        : "+f"(d[0]), "+f"(d[1]), "+f"(d[2]), "+f"(d[3])
        : "r"(a[0]), "r"(a[1]), "r"(a[2]), "r"(a[3]), "r"(b[0]), "r"(b[1]));
}
// 2^y, degree-4 Taylor on [-0.5,0.5] (rel err ~6e-5). |y| bounded by LN'd Q/K.
__device__ __forceinline__ float exp2_nomax(float y) {
    float t = y + 12582912.0f;                 // 1.5*2^23: round-to-nearest
    int ibits = __float_as_int(t) << 23;
    float f = y - (t - 12582912.0f);           // f in [-0.5, 0.5]
    float p = 9.6181e-3f;
    p = fmaf(p, f, 5.5504108664e-2f);
    p = fmaf(p, f, 2.4022650696e-1f);
    p = fmaf(p, f, 6.9314718056e-1f);
    p = fmaf(p, f, 1.0f);
    return __int_as_float(__float_as_int(p) + ibits);
}

// ===========================================================================
// fp32 -> bf16 conversion: ONE kernel for all weights + emb.
// grid (512, 8): z 0..3 -> Wq/Wk/Wv/Wu into g_Wh; z 4..7 -> emb quarters
// into g_EmbH. Each z covers 1M elements, 8 per thread.
// ===========================================================================
__global__ __launch_bounds__(256) void conv_all_kernel(
    const float* __restrict__ Wq, const float* __restrict__ Wk,
    const float* __restrict__ Wv, const float* __restrict__ Wu,
    const float* __restrict__ emb)
{
    const int z = blockIdx.y;
    const size_t M1 = (size_t)EE * HD;  // 1M elements
    const float* src;
    __nv_bfloat16* dst;
    if (z < 4) {
        src = (z == 0) ? Wq : (z == 1) ? Wk : (z == 2) ? Wv : Wu;
        dst = g_Wh + (size_t)z * M1;
    } else {
        src = emb + (size_t)(z - 4) * M1;
        dst = g_EmbH + (size_t)(z - 4) * M1;
    }
    int i = blockIdx.x * blockDim.x + threadIdx.x;   // over 1M/8
    float4 a = ((const float4*)src)[2 * i + 0];
    float4 b = ((const float4*)src)[2 * i + 1];
    __nv_bfloat162* d = (__nv_bfloat162*)dst + 4 * i;
    d[0] = __halves2bfloat162(__float2bfloat16(a.x), __float2bfloat16(a.y));
    d[1] = __halves2bfloat162(__float2bfloat16(a.z), __float2bfloat16(a.w));
    d[2] = __halves2bfloat162(__float2bfloat16(b.x), __float2bfloat16(b.y));
    d[3] = __halves2bfloat162(__float2bfloat16(b.z), __float2bfloat16(b.w));
}

// ===========================================================================
// bf16 mma.sync GEMM: C[m,n] = sum_k A[m,k]*B[n,k]
// Block 128x128, BK=32, 8 warps (warp tile 32x64), cp.async THREE-stage
// pipeline, __launch_bounds__(256,2) -> 2 CTAs/SM.
// Epilogue modes: z==2 -> bf16 to g_Vh; emb!=null -> fp32 + bu + emb residual;
// else -> fused per-head LayerNorm -> bf16 to g_Qh (z=0, 0.125*log2e) / g_Kh.
// ===========================================================================
#define ASTR 40
#define TILE_BYTES (128 * ASTR * 2)       // 10240
#define STAGE_BYTES (2 * TILE_BYTES)      // 20480
#define GEMM_SMEM (3 * STAGE_BYTES)       // 61440

__global__ __launch_bounds__(256, 2) void mma_gemm_kernel(
    const __nv_bfloat16* __restrict__ A,
    const __nv_bfloat16* __restrict__ Wall,
    float* Cout,
    const float* __restrict__ emb, const float* __restrict__ bu,
    const float* __restrict__ qn_w, const float* __restrict__ qn_b,
    const float* __restrict__ kn_w, const float* __restrict__ kn_b)
{
    extern __shared__ char smem[];
    const uint32_t sb = smem_to_u32(smem);
    const int tid = threadIdx.x;
    const int wid = tid >> 5, lane = tid & 31;
    const int bn = blockIdx.x * 128;
    const int bm = blockIdx.y * 128;
    const int z = blockIdx.z;

    const __nv_bfloat16* Bp = Wall + (size_t)z * EE * HD;
    const int wm = wid & 3;
    const int wn = wid >> 2;

    float acc[2][8][4];
#pragma unroll
    for (int mt = 0; mt < 2; mt++)
#pragma unroll
        for (int nt = 0; nt < 8; nt++)
#pragma unroll
            for (int e = 0; e < 4; e++) acc[mt][nt][e] = 0.0f;

#define LOAD_STAGE(st, kt) do { \
    _Pragma("unroll") \
    for (int it = 0; it < 4; it++) { \
        int idx = tid + it * 256; \
        int tile = idx >> 9, rem = idx & 511, row = rem >> 2, seg = rem & 3; \
        const __nv_bfloat16* srcp = tile ? Bp : A; \
        int grow = (tile ? bn : bm) + row; \
        uint32_t dst = sb + (st) * STAGE_BYTES + tile * TILE_BYTES \
                       + (uint32_t)(row * ASTR + seg * 8) * 2; \
        cp16(dst, srcp + (size_t)grow * 1024 + (kt) + seg * 8); \
    } \
    cp_commit(); \
} while (0)

    LOAD_STAGE(0, 0);
    LOAD_STAGE(1, 32);

    int stage = 0;
    for (int ch = 0; ch < 32; ch++) {
        if (ch < 30) {
            int nst = stage + 2; if (nst >= 3) nst -= 3;
            LOAD_STAGE(nst, (ch + 2) * 32);
            cp_wait<2>();
        } else if (ch == 30) {
            cp_wait<1>();
        } else {
            cp_wait<0>();
        }
        __syncthreads();

        const uint32_t aA = sb + stage * STAGE_BYTES;
        const uint32_t aB = aA + TILE_BYTES;

#pragma unroll
        for (int kk = 0; kk < 2; kk++) {
            const int k0 = kk * 16;
            uint32_t ah[2][4], bh[8][2];
#pragma unroll
            for (int mt = 0; mt < 2; mt++) {
                int mrow = wm * 32 + mt * 16 + ((lane >> 3) & 1) * 8 + (lane & 7);
                int mcol = k0 + (lane >> 4) * 8;
                ldm_x4(ah[mt], aA + (uint32_t)(mrow * ASTR + mcol) * 2);
            }
#pragma unroll
            for (int np = 0; np < 4; np++) {
                int nrow = wn * 64 + np * 16 + (lane >> 4) * 8 + (lane & 7);
                int ncol = k0 + ((lane >> 3) & 1) * 8;
                uint32_t r[4];
                ldm_x4(r, aB + (uint32_t)(nrow * ASTR + ncol) * 2);
                bh[np * 2][0] = r[0]; bh[np * 2][1] = r[1];
                bh[np * 2 + 1][0] = r[2]; bh[np * 2 + 1][1] = r[3];
            }
#pragma unroll
            for (int mt = 0; mt < 2; mt++)
#pragma unroll
                for (int nt = 0; nt < 8; nt++) mma_bf16(acc[mt][nt], ah[mt], bh[nt]);
        }
        __syncthreads();
        if (++stage == 3) stage = 0;
    }

    const int tig = lane & 3, gid = lane >> 2;
    if (z == 2) {
        // V: write bf16 directly
#pragma unroll
        for (int mt = 0; mt < 2; mt++) {
            int r0 = bm + wm * 32 + mt * 16 + gid;
#pragma unroll
            for (int nt = 0; nt < 8; nt++) {
                int n = bn + wn * 64 + nt * 8 + tig * 2;
                *(__nv_bfloat162*)(g_Vh + (size_t)r0 * HD + n) =
                    __halves2bfloat162(__float2bfloat16(acc[mt][nt][0]),
                                       __float2bfloat16(acc[mt][nt][1]));
                *(__nv_bfloat162*)(g_Vh + (size_t)(r0 + 8) * HD + n) =
                    __halves2bfloat162(__float2bfloat16(acc[mt][nt][2]),
                                       __float2bfloat16(acc[mt][nt][3]));
            }
        }
    } else if (emb) {
        // out-projection epilogue: + bu + emb residual, fp32 output
#pragma unroll
        for (int mt = 0; mt < 2; mt++) {
            int r0 = bm + wm * 32 + mt * 16 + gid;
#pragma unroll
            for (int nt = 0; nt < 8; nt++) {
                int n = bn + wn * 64 + nt * 8 + tig * 2;
                float2 v0 = make_float2(acc[mt][nt][0], acc[mt][nt][1]);
                float2 v1 = make_float2(acc[mt][nt][2], acc[mt][nt][3]);
                float b0 = bu[n], b1 = bu[n + 1];
                float2 e0 = *(const float2*)(emb + (size_t)r0 * EE + n);
                float2 e1 = *(const float2*)(emb + (size_t)(r0 + 8) * EE + n);
                v0.x += b0 + e0.x; v0.y += b1 + e0.y;
                v1.x += b0 + e1.x; v1.y += b1 + e1.y;
                *(float2*)(Cout + (size_t)r0 * 1024 + n) = v0;
                *(float2*)(Cout + (size_t)(r0 + 8) * 1024 + n) = v1;
            }
        }
    } else {
        // fused LayerNorm epilogue (Q: z==0 with folded 0.125*log2e; K: z==1)
        const float scale = (z == 0) ? 0.1803368801111243f : 1.0f;
        const float* lw = (z == 0) ? qn_w : kn_w;
        const float* lb = (z == 0) ? qn_b : kn_b;
        __nv_bfloat16* dstb = (z == 0) ? g_Qh : g_Kh;
        float wv[16], bv[16];
#pragma unroll
        for (int nt = 0; nt < 8; nt++) {
            int c = nt * 8 + tig * 2;   // column within head
            float2 wp = *(const float2*)(lw + c);
            float2 bp = *(const float2*)(lb + c);
            wv[nt * 2] = wp.x; wv[nt * 2 + 1] = wp.y;
            bv[nt * 2] = bp.x; bv[nt * 2 + 1] = bp.y;
        }
#pragma unroll
        for (int mt = 0; mt < 2; mt++) {
            int r0 = bm + wm * 32 + mt * 16 + gid;
#pragma unroll
            for (int half = 0; half < 2; half++) {
                float sum = 0.0f, sq = 0.0f;
#pragma unroll
                for (int nt = 0; nt < 8; nt++) {
                    float v0 = acc[mt][nt][half * 2];
                    float v1 = acc[mt][nt][half * 2 + 1];
                    sum += v0 + v1;
                    sq = fmaf(v0, v0, sq); sq = fmaf(v1, v1, sq);
                }
                sum += __shfl_xor_sync(0xffffffffu, sum, 1);
                sum += __shfl_xor_sync(0xffffffffu, sum, 2);
                sq  += __shfl_xor_sync(0xffffffffu, sq, 1);
                sq  += __shfl_xor_sync(0xffffffffu, sq, 2);
                float mean = sum * (1.0f / 64.0f);
                float var = sq * (1.0f / 64.0f) - mean * mean;
                float inv = rsqrtf(var + 1e-5f) * scale;
                int row = r0 + half * 8;
#pragma unroll
                for (int nt = 0; nt < 8; nt++) {
                    int n = bn + wn * 64 + nt * 8 + tig * 2;
                    float v0 = acc[mt][nt][half * 2];
                    float v1 = acc[mt][nt][half * 2 + 1];
                    float y0 = fmaf((v0 - mean) * inv, wv[nt * 2],     bv[nt * 2] * scale);
                    float y1 = fmaf((v1 - mean) * inv, wv[nt * 2 + 1], bv[nt * 2 + 1] * scale);
                    *(__nv_bfloat162*)(dstb + (size_t)row * HD + n) =
                        __halves2bfloat162(__float2bfloat16(y0), __float2bfloat16(y1));
                }
            }
        }
    }
}

// ---------------------------------------------------------------------------
// Flash attention on mma.sync (bf16). grid (S/128, B*H), 256 threads (8 warps).
// Warp = 16 q rows. KV tile 128, per-16-col-chunk QK->exp2->PV.
// __launch_bounds__(256,2): 2 CTAs/SM. Max-free softmax. Output bf16.
// ---------------------------------------------------------------------------
#define QSTR 72
#define ATILE (128 * QSTR * 2)
#define KV_OFF ATILE
#define KVSTAGE (2 * ATILE)
#define ATTN_SMEM (ATILE + 2 * KVSTAGE)

__global__ __launch_bounds__(256, 2) void attn_kernel()
{
    extern __shared__ char smem[];
    const uint32_t sb = smem_to_u32(smem);
    const int tid = threadIdx.x;
    const int wid = tid >> 5, lane = tid & 31;
    const int gid = lane >> 2, tig = lane & 3;
    const int q0 = blockIdx.x * 128;
    const int bh = blockIdx.y;
    const int b = bh >> 4, h = bh & 15;

    const __nv_bfloat16* Qg = g_Qh + (size_t)(b * SS + q0) * HD + h * DD;
    const __nv_bfloat16* Kg = g_Kh + (size_t)(b * SS) * HD + h * DD;
    const __nv_bfloat16* Vg = g_Vh + (size_t)(b * SS) * HD + h * DD;

#pragma unroll
    for (int p = 0; p < 4; p++) {
        int idx = tid + p * 256;
        int row = idx >> 3, seg = idx & 7;
        cp16(sb + (uint32_t)(row * QSTR + seg * 8) * 2,
             Qg + (size_t)row * HD + seg * 8);
    }
    cp_commit();

#define LOAD_KV(st, it) do { \
    int kvb = (it) * 128; \
    _Pragma("unroll") \
    for (int p = 0; p < 8; p++) { \
        int idx = tid + p * 256; \
        int tile = idx >> 10, row = (idx >> 3) & 127, seg = idx & 7; \
        const __nv_bfloat16* src = tile ? Vg : Kg; \
        uint32_t dst = sb + KV_OFF + (st) * KVSTAGE + tile * ATILE \
                       + (uint32_t)(row * QSTR + seg * 8) * 2; \
        cp16(dst, src + (size_t)(kvb + row) * HD + seg * 8); \
    } \
    cp_commit(); \
} while (0)

    LOAD_KV(0, 0);
    cp_wait<1>();
    __syncthreads();

    uint32_t qf[4][4];
#pragma unroll
    for (int kk = 0; kk < 4; kk++) {
        int mrow = wid * 16 + ((lane >> 3) & 1) * 8 + (lane & 7);
        int mcol = kk * 16 + (lane >> 4) * 8;
        ldm_x4(qf[kk], sb + (uint32_t)(mrow * QSTR + mcol) * 2);
    }

    float o[8][4];
#pragma unroll
    for (int nt = 0; nt < 8; nt++)
#pragma unroll
        for (int e = 0; e < 4; e++) o[nt][e] = 0.0f;
    float l0 = 0.0f, l1 = 0.0f;

    for (int it = 0; it < 16; it++) {
        if (it < 15) { LOAD_KV((it + 1) & 1, it + 1); cp_wait<1>(); }
        else         { cp_wait<0>(); }
        __syncthreads();

        const uint32_t Kb = sb + KV_OFF + (it & 1) * KVSTAGE;
        const uint32_t Vb = Kb + ATILE;

        // per 16-kv-chunk: QK mma -> exp2 -> P bf16 -> PV mma
#pragma unroll
        for (int t = 0; t < 8; t++) {
            float s0[4] = {0.0f, 0.0f, 0.0f, 0.0f};
            float s1[4] = {0.0f, 0.0f, 0.0f, 0.0f};
            const int nrow = t * 16 + (lane >> 4) * 8 + (lane & 7);
#pragma unroll
            for (int kk = 0; kk < 4; kk++) {
                int ncol = kk * 16 + ((lane >> 3) & 1) * 8;
                uint32_t r[4];
                ldm_x4(r, Kb + (uint32_t)(nrow * QSTR + ncol) * 2);
                mma_bf16(s0, qf[kk], r);
                mma_bf16(s1, qf[kk], r + 2);
            }
            s0[0] = exp2_nomax(s0[0]); s0[1] = exp2_nomax(s0[1]);
            s0[2] = exp2_nomax(s0[2]); s0[3] = exp2_nomax(s0[3]);
            s1[0] = exp2_nomax(s1[0]); s1[1] = exp2_nomax(s1[1]);
            s1[2] = exp2_nomax(s1[2]); s1[3] = exp2_nomax(s1[3]);
            l0 += s0[0] + s0[1] + s1[0] + s1[1];
            l1 += s0[2] + s0[3] + s1[2] + s1[3];

            uint32_t pa[4];
            asm("cvt.rn.bf16x2.f32 %0, %1, %2;" : "=r"(pa[0]) : "f"(s0[1]), "f"(s0[0]));
            asm("cvt.rn.bf16x2.f32 %0, %1, %2;" : "=r"(pa[1]) : "f"(s0[3]), "f"(s0[2]));
            asm("cvt.rn.bf16x2.f32 %0, %1, %2;" : "=r"(pa[2]) : "f"(s1[1]), "f"(s1[0]));
            asm("cvt.rn.bf16x2.f32 %0, %1, %2;" : "=r"(pa[3]) : "f"(s1[3]), "f"(s1[2]));

            const int kvrow = t * 16 + ((lane >> 3) & 1) * 8 + (lane & 7);
#pragma unroll
            for (int nh = 0; nh < 4; nh++) {
                int col = nh * 16 + (lane >> 4) * 8;
                uint32_t r[4];
                ldm_x4_t(r, Vb + (uint32_t)(kvrow * QSTR + col) * 2);
                mma_bf16(o[nh * 2],     pa, r);
                mma_bf16(o[nh * 2 + 1], pa, r + 2);
            }
        }
        __syncthreads();
    }

    // reduce l over the tig group once
    l0 += __shfl_xor_sync(0xffffffffu, l0, 1);
    l0 += __shfl_xor_sync(0xffffffffu, l0, 2);
    l1 += __shfl_xor_sync(0xffffffffu, l1, 1);
    l1 += __shfl_xor_sync(0xffffffffu, l1, 2);

    const float rl0 = 1.0f / l0, rl1 = 1.0f / l1;
    const size_t row0 = (size_t)(b * SS + q0 + wid * 16 + gid) * HD;
    const size_t row1 = row0 + 8 * HD;
#pragma unroll
    for (int nt = 0; nt < 8; nt++) {
        int col = h * DD + nt * 8 + 2 * tig;
        *(__nv_bfloat162*)(g_AttnH + row0 + col) =
            __halves2bfloat162(__float2bfloat16(o[nt][0] * rl0),
                               __float2bfloat16(o[nt][1] * rl0));
        *(__nv_bfloat162*)(g_AttnH + row1 + col) =
            __halves2bfloat162(__float2bfloat16(o[nt][2] * rl1),
                               __float2bfloat16(o[nt][3] * rl1));
    }
}

// ---------------------------------------------------------------------------
extern "C" void kernel_launch(void* const* d_in, const int* in_sizes, int n_in,
                              void* d_out, int out_size)
{
    const float* emb  = (const float*)d_in[0];
    const float* Wq   = (const float*)d_in[1];
    const float* Wk   = (const float*)d_in[2];
    const float* Wv   = (const float*)d_in[3];
    const float* Wu   = (const float*)d_in[4];
    const float* bu   = (const float*)d_in[5];
    const float* qn_w = (const float*)d_in[6];
    const float* qn_b = (const float*)d_in[7];
    const float* kn_w = (const float*)d_in[8];
    const float* kn_b = (const float*)d_in[9];
    float* out = (float*)d_out;

    (void)in_sizes; (void)n_in; (void)out_size;

    cudaFuncSetAttribute(attn_kernel,
                         cudaFuncAttributeMaxDynamicSharedMemorySize, ATTN_SMEM);
    cudaFuncSetAttribute(mma_gemm_kernel,
                         cudaFuncAttributeMaxDynamicSharedMemorySize, GEMM_SMEM);

    __nv_bfloat16 *EmbH_p, *AttnH_p, *Wh_p;
    cudaGetSymbolAddress((void**)&EmbH_p, g_EmbH);
    cudaGetSymbolAddress((void**)&AttnH_p, g_AttnH);
    cudaGetSymbolAddress((void**)&Wh_p, g_Wh);

    // 1) emb + all weights -> bf16 (single launch)
    conv_all_kernel<<<dim3((EE * HD / 8) / 256, 8), 256>>>(Wq, Wk, Wv, Wu, emb);

    // 2) QKV projections with fused LayerNorm epilogue -> Qh/Kh/Vh (bf16)
    mma_gemm_kernel<<<dim3(HD / 128, MTOT / 128, 3), 256, GEMM_SMEM>>>(
        EmbH_p, Wh_p, nullptr, nullptr, nullptr, qn_w, qn_b, kn_w, kn_b);

    // 3) Attention (tensor cores + max-free FMA-pipe exp2) -> g_AttnH (bf16)
    attn_kernel<<<dim3(SS / 128, BB * HH), 256, ATTN_SMEM>>>();

    // 4) Output projection + bias + residual
    mma_gemm_kernel<<<dim3(EE / 128, MTOT / 128, 1), 256, GEMM_SMEM>>>(
        AttnH_p, Wh_p + (size_t)3 * EE * HD, out, emb, bu,
        nullptr, nullptr, nullptr, nullptr);
}